// round 4
// baseline (speedup 1.0000x reference)
#include <cuda_runtime.h>
#include <cuda_bf16.h>
#include <stdint.h>

#define NB 8
#define NS 2048
#define ND 1024
#define NROWS (NB * NS)          // 16384
#define WSZ ((size_t)ND * ND)

// ---------------- scratch (no cudaMalloc allowed) ----------------
__device__ __nv_bfloat16 g_xn_h [(size_t)NROWS * ND], g_xn_l [(size_t)NROWS * ND];
__device__ __nv_bfloat16 g_q_h  [(size_t)NROWS * ND], g_q_l  [(size_t)NROWS * ND];
__device__ __nv_bfloat16 g_k_h  [(size_t)NROWS * ND], g_k_l  [(size_t)NROWS * ND];
__device__ __nv_bfloat16 g_kT_h [(size_t)NROWS * ND], g_kT_l [(size_t)NROWS * ND];
__device__ __nv_bfloat16 g_w_h  [(size_t)NB * NS * NS], g_w_l [(size_t)NB * NS * NS];
__device__ __nv_bfloat16 g_at_h [(size_t)NROWS * ND], g_at_l [(size_t)NROWS * ND];
__device__ float         g_x2   [(size_t)NROWS * ND];
__device__ __nv_bfloat16 g_xn2_h[(size_t)NROWS * ND], g_xn2_l[(size_t)NROWS * ND];
__device__ __nv_bfloat16 g_h_h  [(size_t)NROWS * ND], g_h_l  [(size_t)NROWS * ND];
__device__ __nv_bfloat16 g_wt   [5 * 2 * WSZ];

// ---------------- helpers ----------------
__device__ __forceinline__ uint32_t smem_u32(const void* p) {
    uint32_t a;
    asm("{ .reg .u64 t; cvta.to.shared.u64 t, %1; cvt.u32.u64 %0, t; }" : "=r"(a) : "l"(p));
    return a;
}
__device__ __forceinline__ void cp16(uint32_t dst, const void* src) {
    asm volatile("cp.async.cg.shared.global [%0], [%1], 16;" :: "r"(dst), "l"(src));
}
__device__ __forceinline__ void ldm4(uint32_t* a, uint32_t addr) {
    asm volatile("ldmatrix.sync.aligned.m8n8.x4.shared.b16 {%0,%1,%2,%3}, [%4];"
                 : "=r"(a[0]), "=r"(a[1]), "=r"(a[2]), "=r"(a[3]) : "r"(addr));
}
__device__ __forceinline__ void mma16816(float* c, const uint32_t* a, const uint32_t* b) {
    asm volatile("mma.sync.aligned.m16n8k16.row.col.f32.bf16.bf16.f32 "
                 "{%0,%1,%2,%3}, {%4,%5,%6,%7}, {%8,%9}, {%0,%1,%2,%3};"
                 : "+f"(c[0]), "+f"(c[1]), "+f"(c[2]), "+f"(c[3])
                 : "r"(a[0]), "r"(a[1]), "r"(a[2]), "r"(a[3]), "r"(b[0]), "r"(b[1]));
}

// smem stage: A_h 8K | A_l 8K | B_h 16K | B_l 16K = 48KB; 3 stages
#define STAGE  49152
#define NSTG   3
#define SMEMSZ (NSTG * STAGE)

// ---------------- warp-MMA split-bf16 GEMM: 128x256 CTA tile, kchunk 32 ----------------
// D = alpha * A[M,K] * B[N,K]^T  (+bias) (mask==0 -> -1e9) (+resid) (relu)
// 8 warps as 2(m) x 4(n); warp tile 64x64; 3 MMA passes (hh, hl, lh)
template <bool BIAS, bool RELU, bool MASK, bool RESID, bool HILO>
__global__ void __launch_bounds__(256, 1) gemm_tc(
    const __nv_bfloat16* __restrict__ Ahi, const __nv_bfloat16* __restrict__ Alo,
    const __nv_bfloat16* __restrict__ Bhi, const __nv_bfloat16* __restrict__ Blo,
    int M, int N, int K,
    long long sA, long long sB, long long sC,
    float* __restrict__ Cf,
    __nv_bfloat16* __restrict__ Chi, __nv_bfloat16* __restrict__ Clo,
    const float* __restrict__ bias,
    const float* __restrict__ resid,
    const int* __restrict__ mask,
    float alpha)
{
    extern __shared__ char smem[];
    const int tid  = threadIdx.x;
    const int lane = tid & 31, wid = tid >> 5;
    const int wm = wid & 1, wn = wid >> 1;          // 2 x 4 warp grid
    const int bz = blockIdx.z;
    const size_t aoff = (size_t)bz * sA, boff = (size_t)bz * sB, coff = (size_t)bz * sC;
    Ahi += aoff; Alo += aoff; Bhi += boff; Blo += boff;
    if (!HILO) Cf += coff; else { Chi += coff; Clo += coff; }
    const int m0 = blockIdx.y * 128, n0 = blockIdx.x * 256;

    const uint32_t sb = smem_u32(smem);

    float acc[4][8][4];
#pragma unroll
    for (int i = 0; i < 4; i++)
#pragma unroll
        for (int j = 0; j < 8; j++)
#pragma unroll
            for (int q = 0; q < 4; q++) acc[i][j][q] = 0.f;

    const int nk = K >> 5;

    // staging maps (tiles are contiguous 8x8 bf16 = 128B blocks, column of tiles per kt8)
    // A block: 128 rows x 32k = 512 x 16B vectors; B block: 256 rows -> 1024 vectors
    auto issue = [&](int i) {
        const uint32_t s = sb + (uint32_t)(i % NSTG) * STAGE;
        const int k0 = i << 5;
#pragma unroll
        for (int h = 0; h < 2; h++) {                 // A: 2 vec16 per thread
            const int idx = tid + h * 256;
            const int row = idx >> 2, kt = idx & 3;
            const uint32_t off = (uint32_t)((kt * 16 + (row >> 3)) * 128 + (row & 7) * 16);
            const size_t g = (size_t)(m0 + row) * K + k0 + kt * 8;
            cp16(s + off,        Ahi + g);
            cp16(s + 8192 + off, Alo + g);
        }
#pragma unroll
        for (int h = 0; h < 4; h++) {                 // B: 4 vec16 per thread
            const int idx = tid + h * 256;
            const int row = idx >> 2, kt = idx & 3;
            const uint32_t off = (uint32_t)((kt * 32 + (row >> 3)) * 128 + (row & 7) * 16);
            const size_t g = (size_t)(n0 + row) * K + k0 + kt * 8;
            cp16(s + 16384 + off, Bhi + g);
            cp16(s + 32768 + off, Blo + g);
        }
        asm volatile("cp.async.commit_group;");
    };

    issue(0);
    issue(1);
    const int mrow16 = (lane & 7) * 16;

    for (int i = 0; i < nk; i++) {
        if (i == nk - 1) asm volatile("cp.async.wait_group 0;");
        else             asm volatile("cp.async.wait_group 1;");
        __syncthreads();
        if (i + 2 < nk) issue(i + 2);

        const uint32_t st   = sb + (uint32_t)(i % NSTG) * STAGE;
        const uint32_t sA_h = st;
        const uint32_t sA_l = st + 8192;
        const uint32_t sB_h = st + 16384;
        const uint32_t sB_l = st + 32768;

#pragma unroll
        for (int ks = 0; ks < 2; ks++) {
            // B fragments for all 8 n-tiles, hi and lo (x4 loads 2 adjacent n-tiles)
            uint32_t bh[8][2], bl[8][2];
            const int bksub = ks * 2 + ((lane >> 3) & 1);     // k-subtile per lane group
            const int bnt   = (lane >> 4);                    // n-tile offset per lane group
#pragma unroll
            for (int p = 0; p < 4; p++) {
                const int nt8 = wn * 8 + p * 2;
                const uint32_t off = (uint32_t)((bksub * 32 + nt8 + bnt) * 128) + mrow16;
                uint32_t th[4], tl[4];
                ldm4(th, sB_h + off);
                ldm4(tl, sB_l + off);
                bh[p*2][0]   = th[0]; bh[p*2][1]   = th[1];
                bh[p*2+1][0] = th[2]; bh[p*2+1][1] = th[3];
                bl[p*2][0]   = tl[0]; bl[p*2][1]   = tl[1];
                bl[p*2+1][0] = tl[2]; bl[p*2+1][1] = tl[3];
            }
            const int dm = (lane >> 3) & 1, dk = lane >> 4;
#pragma unroll
            for (int mt = 0; mt < 4; mt++) {
                const int mt8 = wm * 8 + mt * 2 + dm;
                const uint32_t off = (uint32_t)(((ks * 2 + dk) * 16 + mt8) * 128) + mrow16;
                uint32_t ah[4], al[4];
                ldm4(ah, sA_h + off);
                ldm4(al, sA_l + off);
#pragma unroll
                for (int nt = 0; nt < 8; nt++) {
                    mma16816(acc[mt][nt], ah, bh[nt]);
                    mma16816(acc[mt][nt], ah, bl[nt]);
                    mma16816(acc[mt][nt], al, bh[nt]);
                }
            }
        }
    }

    // ---------------- epilogue ----------------
    const int cq = (lane & 3) * 2, rq = lane >> 2;
#pragma unroll
    for (int nt = 0; nt < 8; nt++) {
        const int c = n0 + wn * 64 + nt * 8 + cq;
        float bv0 = 0.f, bv1 = 0.f;
        if (BIAS) { bv0 = bias[c]; bv1 = bias[c + 1]; }
        int mk0 = 1, mk1 = 1;
        if (MASK) {
            const int* mp = mask + (size_t)bz * N;
            mk0 = mp[c]; mk1 = mp[c + 1];
        }
#pragma unroll
        for (int mt = 0; mt < 4; mt++) {
            const int r0 = m0 + wm * 64 + mt * 16 + rq;
#pragma unroll
            for (int h = 0; h < 2; h++) {
                const int row = r0 + h * 8;
                float v0 = acc[mt][nt][h * 2 + 0] * alpha + bv0;
                float v1 = acc[mt][nt][h * 2 + 1] * alpha + bv1;
                if (MASK) { if (mk0 == 0) v0 = -1e9f; if (mk1 == 0) v1 = -1e9f; }
                if (RESID) {
                    float2 rv = *(const float2*)(resid + (size_t)row * N + c);
                    v0 += rv.x; v1 += rv.y;
                }
                if (RELU) { v0 = fmaxf(v0, 0.f); v1 = fmaxf(v1, 0.f); }
                if (HILO) {
                    __nv_bfloat16 h0 = __float2bfloat16(v0);
                    __nv_bfloat16 h1 = __float2bfloat16(v1);
                    *(__nv_bfloat162*)(Chi + (size_t)row * N + c) = __halves2bfloat162(h0, h1);
                    *(__nv_bfloat162*)(Clo + (size_t)row * N + c) =
                        __floats2bfloat162_rn(v0 - __bfloat162float(h0),
                                              v1 - __bfloat162float(h1));
                } else {
                    *(float2*)(Cf + (size_t)row * N + c) = make_float2(v0, v1);
                }
            }
        }
    }
}

// ---------------- LayerNorm -> bf16 hi/lo ----------------
__global__ void __launch_bounds__(256) ln_hilo(const float* __restrict__ x,
                                               const float* __restrict__ g,
                                               const float* __restrict__ b,
                                               __nv_bfloat16* __restrict__ oh,
                                               __nv_bfloat16* __restrict__ ol)
{
    size_t row = blockIdx.x;
    int t = threadIdx.x;
    float4 xv = ((const float4*)(x + row * ND))[t];
    float s  = xv.x + xv.y + xv.z + xv.w;
    float ss = xv.x*xv.x + xv.y*xv.y + xv.z*xv.z + xv.w*xv.w;
#pragma unroll
    for (int o = 16; o; o >>= 1) {
        s  += __shfl_xor_sync(0xffffffffu, s,  o);
        ss += __shfl_xor_sync(0xffffffffu, ss, o);
    }
    __shared__ float sh_s[8], sh_ss[8];
    if ((t & 31) == 0) { sh_s[t >> 5] = s; sh_ss[t >> 5] = ss; }
    __syncthreads();
    float ts = 0.f, tss = 0.f;
#pragma unroll
    for (int i = 0; i < 8; i++) { ts += sh_s[i]; tss += sh_ss[i]; }
    float mean = ts * (1.f / ND);
    float var  = tss * (1.f / ND) - mean * mean;
    float rstd = rsqrtf(var + 1e-5f);
    float4 gv = ((const float4*)g)[t];
    float4 bv = ((const float4*)b)[t];
    float o0 = (xv.x - mean) * rstd * gv.x + bv.x;
    float o1 = (xv.y - mean) * rstd * gv.y + bv.y;
    float o2 = (xv.z - mean) * rstd * gv.z + bv.z;
    float o3 = (xv.w - mean) * rstd * gv.w + bv.w;
    __nv_bfloat16 h0 = __float2bfloat16(o0), h1 = __float2bfloat16(o1);
    __nv_bfloat16 h2 = __float2bfloat16(o2), h3 = __float2bfloat16(o3);
    __nv_bfloat162* ph = (__nv_bfloat162*)(oh + row * ND);
    __nv_bfloat162* pl = (__nv_bfloat162*)(ol + row * ND);
    ph[2*t]   = __halves2bfloat162(h0, h1);
    ph[2*t+1] = __halves2bfloat162(h2, h3);
    pl[2*t]   = __floats2bfloat162_rn(o0 - __bfloat162float(h0), o1 - __bfloat162float(h1));
    pl[2*t+1] = __floats2bfloat162_rn(o2 - __bfloat162float(h2), o3 - __bfloat162float(h3));
}

// ---------------- softmax (in-place fp32) + bf16 hi/lo ----------------
__global__ void __launch_bounds__(256) softmax_hilo(float* __restrict__ w,
                                                    __nv_bfloat16* __restrict__ oh,
                                                    __nv_bfloat16* __restrict__ ol)
{
    float* p = w + (size_t)blockIdx.x * NS;
    int t = threadIdx.x;
    float4 v0 = ((const float4*)p)[t];
    float4 v1 = ((const float4*)p)[t + 256];
    float mx = fmaxf(fmaxf(fmaxf(v0.x, v0.y), fmaxf(v0.z, v0.w)),
                     fmaxf(fmaxf(v1.x, v1.y), fmaxf(v1.z, v1.w)));
#pragma unroll
    for (int o = 16; o; o >>= 1) mx = fmaxf(mx, __shfl_xor_sync(0xffffffffu, mx, o));
    __shared__ float shm[8], shs[8];
    if ((t & 31) == 0) shm[t >> 5] = mx;
    __syncthreads();
    mx = shm[0];
#pragma unroll
    for (int i = 1; i < 8; i++) mx = fmaxf(mx, shm[i]);
    float e[8];
    e[0] = __expf(v0.x - mx); e[1] = __expf(v0.y - mx);
    e[2] = __expf(v0.z - mx); e[3] = __expf(v0.w - mx);
    e[4] = __expf(v1.x - mx); e[5] = __expf(v1.y - mx);
    e[6] = __expf(v1.z - mx); e[7] = __expf(v1.w - mx);
    float s = e[0]+e[1]+e[2]+e[3]+e[4]+e[5]+e[6]+e[7];
#pragma unroll
    for (int o = 16; o; o >>= 1) s += __shfl_xor_sync(0xffffffffu, s, o);
    if ((t & 31) == 0) shs[t >> 5] = s;
    __syncthreads();
    s = 0.f;
#pragma unroll
    for (int i = 0; i < 8; i++) s += shs[i];
    float inv = 1.f / s;
#pragma unroll
    for (int i = 0; i < 8; i++) e[i] *= inv;
    ((float4*)p)[t]       = make_float4(e[0], e[1], e[2], e[3]);
    ((float4*)p)[t + 256] = make_float4(e[4], e[5], e[6], e[7]);

    __nv_bfloat162* ph = (__nv_bfloat162*)(oh + (size_t)blockIdx.x * NS);
    __nv_bfloat162* pl = (__nv_bfloat162*)(ol + (size_t)blockIdx.x * NS);
#pragma unroll
    for (int q = 0; q < 2; q++) {
        int base = q ? 512 : 0;
        int ei = q * 4;
        __nv_bfloat16 h0 = __float2bfloat16(e[ei+0]);
        __nv_bfloat16 h1 = __float2bfloat16(e[ei+1]);
        __nv_bfloat16 h2 = __float2bfloat16(e[ei+2]);
        __nv_bfloat16 h3 = __float2bfloat16(e[ei+3]);
        ph[base + 2*t]   = __halves2bfloat162(h0, h1);
        ph[base + 2*t+1] = __halves2bfloat162(h2, h3);
        pl[base + 2*t]   = __floats2bfloat162_rn(e[ei+0] - __bfloat162float(h0),
                                                 e[ei+1] - __bfloat162float(h1));
        pl[base + 2*t+1] = __floats2bfloat162_rn(e[ei+2] - __bfloat162float(h2),
                                                 e[ei+3] - __bfloat162float(h3));
    }
}

// ---------------- weight transpose + split ----------------
__global__ void __launch_bounds__(256) wt_conv(const float* __restrict__ W,
                                               __nv_bfloat16* __restrict__ Th,
                                               __nv_bfloat16* __restrict__ Tl)
{
    __shared__ float tile[64][65];
    int k0 = blockIdx.y * 64, n0 = blockIdx.x * 64;
#pragma unroll
    for (int u = threadIdx.x; u < 4096; u += 256) {
        int r = u >> 6, c = u & 63;
        tile[r][c] = W[(size_t)(k0 + r) * ND + n0 + c];
    }
    __syncthreads();
#pragma unroll
    for (int u = threadIdx.x; u < 4096; u += 256) {
        int r = u >> 6, c = u & 63;
        float v = tile[c][r];
        __nv_bfloat16 h = __float2bfloat16(v);
        Th[(size_t)(n0 + r) * ND + k0 + c] = h;
        Tl[(size_t)(n0 + r) * ND + k0 + c] = __float2bfloat16(v - __bfloat162float(h));
    }
}

// ---------------- bf16 transpose (k -> kT per batch) ----------------
__global__ void __launch_bounds__(256) kt_kernel(const __nv_bfloat16* __restrict__ ih,
                                                 const __nv_bfloat16* __restrict__ il,
                                                 __nv_bfloat16* __restrict__ oh,
                                                 __nv_bfloat16* __restrict__ ol)
{
    __shared__ __nv_bfloat16 th[64][65], tl[64][65];
    int b = blockIdx.z;
    int d0 = blockIdx.x * 64, s0 = blockIdx.y * 64;
    const size_t ib = (size_t)b * NS * ND;
    const size_t ob = (size_t)b * ND * NS;
#pragma unroll
    for (int u = threadIdx.x; u < 4096; u += 256) {
        int r = u >> 6, c = u & 63;
        th[r][c] = ih[ib + (size_t)(s0 + r) * ND + d0 + c];
        tl[r][c] = il[ib + (size_t)(s0 + r) * ND + d0 + c];
    }
    __syncthreads();
#pragma unroll
    for (int u = threadIdx.x; u < 4096; u += 256) {
        int r = u >> 6, c = u & 63;
        oh[ob + (size_t)(d0 + r) * NS + s0 + c] = th[c][r];
        ol[ob + (size_t)(d0 + r) * NS + s0 + c] = tl[c][r];
    }
}

// ---------------- driver ----------------
extern "C" void kernel_launch(void* const* d_in, const int* in_sizes, int n_in,
                              void* d_out, int out_size)
{
    const float* x    = (const float*)d_in[0];
    const int*   mask = (const int*)  d_in[1];
    const float* ln1g = (const float*)d_in[2];
    const float* ln1b = (const float*)d_in[3];
    const float* Wq   = (const float*)d_in[4];
    const float* bq   = (const float*)d_in[5];
    const float* Wk   = (const float*)d_in[6];
    const float* bk   = (const float*)d_in[7];
    const float* Wo   = (const float*)d_in[8];
    const float* bo   = (const float*)d_in[9];
    const float* ln2g = (const float*)d_in[10];
    const float* ln2b = (const float*)d_in[11];
    const float* W1   = (const float*)d_in[12];
    const float* b1   = (const float*)d_in[13];
    const float* W2   = (const float*)d_in[14];
    const float* b2   = (const float*)d_in[15];

    float* out  = (float*)d_out;
    float* wout = out + (size_t)NROWS * ND;

    __nv_bfloat16 *xn_h, *xn_l, *q_h, *q_l, *k_h, *k_l, *kT_h, *kT_l;
    __nv_bfloat16 *w_h, *w_l, *at_h, *at_l, *xn2_h, *xn2_l, *h_h, *h_l, *wt;
    float* x2;
    cudaGetSymbolAddress((void**)&xn_h, g_xn_h);   cudaGetSymbolAddress((void**)&xn_l, g_xn_l);
    cudaGetSymbolAddress((void**)&q_h,  g_q_h);    cudaGetSymbolAddress((void**)&q_l,  g_q_l);
    cudaGetSymbolAddress((void**)&k_h,  g_k_h);    cudaGetSymbolAddress((void**)&k_l,  g_k_l);
    cudaGetSymbolAddress((void**)&kT_h, g_kT_h);   cudaGetSymbolAddress((void**)&kT_l, g_kT_l);
    cudaGetSymbolAddress((void**)&w_h,  g_w_h);    cudaGetSymbolAddress((void**)&w_l,  g_w_l);
    cudaGetSymbolAddress((void**)&at_h, g_at_h);   cudaGetSymbolAddress((void**)&at_l, g_at_l);
    cudaGetSymbolAddress((void**)&xn2_h,g_xn2_h);  cudaGetSymbolAddress((void**)&xn2_l,g_xn2_l);
    cudaGetSymbolAddress((void**)&h_h,  g_h_h);    cudaGetSymbolAddress((void**)&h_l,  g_h_l);
    cudaGetSymbolAddress((void**)&x2,   g_x2);
    cudaGetSymbolAddress((void**)&wt,   g_wt);

    __nv_bfloat16 *wq_h = wt + 0*2*WSZ, *wq_l = wt + 0*2*WSZ + WSZ;
    __nv_bfloat16 *wk_h = wt + 1*2*WSZ, *wk_l = wt + 1*2*WSZ + WSZ;
    __nv_bfloat16 *wo_h = wt + 2*2*WSZ, *wo_l = wt + 2*2*WSZ + WSZ;
    __nv_bfloat16 *w1_h = wt + 3*2*WSZ, *w1_l = wt + 3*2*WSZ + WSZ;
    __nv_bfloat16 *w2_h = wt + 4*2*WSZ, *w2_l = wt + 4*2*WSZ + WSZ;

    cudaFuncSetAttribute(gemm_tc<true,false,false,false,true>,
                         cudaFuncAttributeMaxDynamicSharedMemorySize, SMEMSZ);
    cudaFuncSetAttribute(gemm_tc<false,false,true,false,false>,
                         cudaFuncAttributeMaxDynamicSharedMemorySize, SMEMSZ);
    cudaFuncSetAttribute(gemm_tc<false,false,false,false,true>,
                         cudaFuncAttributeMaxDynamicSharedMemorySize, SMEMSZ);
    cudaFuncSetAttribute(gemm_tc<true,false,false,true,false>,
                         cudaFuncAttributeMaxDynamicSharedMemorySize, SMEMSZ);
    cudaFuncSetAttribute(gemm_tc<true,true,false,false,true>,
                         cudaFuncAttributeMaxDynamicSharedMemorySize, SMEMSZ);

    dim3 gW(16, 16);
    wt_conv<<<gW, 256>>>(Wq, wq_h, wq_l);
    wt_conv<<<gW, 256>>>(Wk, wk_h, wk_l);
    wt_conv<<<gW, 256>>>(Wo, wo_h, wo_l);
    wt_conv<<<gW, 256>>>(W1, w1_h, w1_l);
    wt_conv<<<gW, 256>>>(W2, w2_h, w2_l);

    // 1) xn = LN1(x)
    ln_hilo<<<NROWS, 256>>>(x, ln1g, ln1b, xn_h, xn_l);

    dim3 gP(ND / 256, NROWS / 128, 1);
    // 2) q, k projections (v == k, faithful reference bug)
    gemm_tc<true,false,false,false,true><<<gP, 256, SMEMSZ>>>(
        xn_h, xn_l, wq_h, wq_l, NROWS, ND, ND, 0, 0, 0,
        nullptr, q_h, q_l, bq, nullptr, nullptr, 1.f);
    gemm_tc<true,false,false,false,true><<<gP, 256, SMEMSZ>>>(
        xn_h, xn_l, wk_h, wk_l, NROWS, ND, ND, 0, 0, 0,
        nullptr, k_h, k_l, bk, nullptr, nullptr, 1.f);

    // 3) kT for attn@v
    kt_kernel<<<dim3(ND / 64, NS / 64, NB), 256>>>(k_h, k_l, kT_h, kT_l);

    // 4) scores = (q @ k^T)/32, masked -> wout (fp32)
    dim3 gS(NS / 256, NS / 128, NB);
    gemm_tc<false,false,true,false,false><<<gS, 256, SMEMSZ>>>(
        q_h, q_l, k_h, k_l, NS, NS, ND,
        (long long)NS * ND, (long long)NS * ND, (long long)NS * NS,
        wout, nullptr, nullptr, nullptr, nullptr, mask, 0.03125f);

    // 5) softmax in place + hi/lo
    softmax_hilo<<<NROWS, 256>>>(wout, w_h, w_l);

    // 6) attn = w @ v  (v == k)
    dim3 gA(ND / 256, NS / 128, NB);
    gemm_tc<false,false,false,false,true><<<gA, 256, SMEMSZ>>>(
        w_h, w_l, kT_h, kT_l, NS, ND, NS,
        (long long)NS * NS, (long long)ND * NS, (long long)NS * ND,
        nullptr, at_h, at_l, nullptr, nullptr, nullptr, 1.f);

    // 7) x2 = x + attn @ Wo + bo
    gemm_tc<true,false,false,true,false><<<gP, 256, SMEMSZ>>>(
        at_h, at_l, wo_h, wo_l, NROWS, ND, ND, 0, 0, 0,
        x2, nullptr, nullptr, bo, x, nullptr, 1.f);

    // 8) xn2 = LN2(x2)
    ln_hilo<<<NROWS, 256>>>(x2, ln2g, ln2b, xn2_h, xn2_l);

    // 9) h = relu(xn2 @ W1 + b1)
    gemm_tc<true,true,false,false,true><<<gP, 256, SMEMSZ>>>(
        xn2_h, xn2_l, w1_h, w1_l, NROWS, ND, ND, 0, 0, 0,
        nullptr, h_h, h_l, b1, nullptr, nullptr, 1.f);

    // 10) out = x2 + h @ W2 + b2
    gemm_tc<true,false,false,true,false><<<gP, 256, SMEMSZ>>>(
        h_h, h_l, w2_h, w2_l, NROWS, ND, ND, 0, 0, 0,
        out, nullptr, nullptr, b2, x2, nullptr, 1.f);
}

// round 5
// speedup vs baseline: 1.0219x; 1.0219x over previous
#include <cuda_runtime.h>
#include <cuda_bf16.h>
#include <stdint.h>

#define NB 8
#define NS 2048
#define ND 1024
#define NROWS (NB * NS)          // 16384
#define WSZ ((size_t)ND * ND)

// ---------------- scratch (no cudaMalloc allowed) ----------------
__device__ __nv_bfloat16 g_xn_h [(size_t)NROWS * ND], g_xn_l [(size_t)NROWS * ND];
__device__ __nv_bfloat16 g_q_h  [(size_t)NROWS * ND], g_q_l  [(size_t)NROWS * ND];
__device__ __nv_bfloat16 g_k_h  [(size_t)NROWS * ND], g_k_l  [(size_t)NROWS * ND];
__device__ __nv_bfloat16 g_kT_h [(size_t)NROWS * ND], g_kT_l [(size_t)NROWS * ND];
__device__ __nv_bfloat16 g_w_h  [(size_t)NB * NS * NS], g_w_l [(size_t)NB * NS * NS];
__device__ __nv_bfloat16 g_at_h [(size_t)NROWS * ND], g_at_l [(size_t)NROWS * ND];
__device__ float         g_x2   [(size_t)NROWS * ND];
__device__ __nv_bfloat16 g_xn2_h[(size_t)NROWS * ND], g_xn2_l[(size_t)NROWS * ND];
__device__ __nv_bfloat16 g_h_h  [(size_t)NROWS * ND], g_h_l  [(size_t)NROWS * ND];
__device__ __nv_bfloat16 g_wt   [5 * 2 * WSZ];

// ---------------- helpers ----------------
__device__ __forceinline__ uint32_t smem_u32(const void* p) {
    uint32_t a;
    asm("{ .reg .u64 t; cvta.to.shared.u64 t, %1; cvt.u32.u64 %0, t; }" : "=r"(a) : "l"(p));
    return a;
}
__device__ __forceinline__ void cp16(uint32_t dst, const void* src) {
    asm volatile("cp.async.cg.shared.global [%0], [%1], 16;" :: "r"(dst), "l"(src));
}
__device__ __forceinline__ void ldm4(uint32_t* a, uint32_t addr) {
    asm volatile("ldmatrix.sync.aligned.m8n8.x4.shared.b16 {%0,%1,%2,%3}, [%4];"
                 : "=r"(a[0]), "=r"(a[1]), "=r"(a[2]), "=r"(a[3]) : "r"(addr));
}
__device__ __forceinline__ void mma16816(float* c, const uint32_t* a, const uint32_t* b) {
    asm volatile("mma.sync.aligned.m16n8k16.row.col.f32.bf16.bf16.f32 "
                 "{%0,%1,%2,%3}, {%4,%5,%6,%7}, {%8,%9}, {%0,%1,%2,%3};"
                 : "+f"(c[0]), "+f"(c[1]), "+f"(c[2]), "+f"(c[3])
                 : "r"(a[0]), "r"(a[1]), "r"(a[2]), "r"(a[3]), "r"(b[0]), "r"(b[1]));
}

// smem stage: A_h 8K | A_l 8K | B_h 16K | B_l 16K = 48KB; 3 stages = 144KB
#define STAGE  49152
#define NSTG   3
#define SMEMSZ (NSTG * STAGE)

// ---------------- warp-MMA split-bf16 GEMM ----------------
// CTA tile 128x256, kchunk 32, 512 threads = 16 warps as 4(m) x 4(n),
// warp tile 32x64, 3 MMA passes (hh, hl, lh).
// D = alpha * A[M,K] * B[N,K]^T  (+bias) (mask==0 -> -1e9) (+resid) (relu)
template <bool BIAS, bool RELU, bool MASK, bool RESID, bool HILO>
__global__ void __launch_bounds__(512, 1) gemm_tc(
    const __nv_bfloat16* __restrict__ Ahi, const __nv_bfloat16* __restrict__ Alo,
    const __nv_bfloat16* __restrict__ Bhi, const __nv_bfloat16* __restrict__ Blo,
    int M, int N, int K,
    long long sA, long long sB, long long sC,
    float* __restrict__ Cf,
    __nv_bfloat16* __restrict__ Chi, __nv_bfloat16* __restrict__ Clo,
    const float* __restrict__ bias,
    const float* __restrict__ resid,
    const int* __restrict__ mask,
    float alpha)
{
    extern __shared__ char smem[];
    const int tid  = threadIdx.x;
    const int lane = tid & 31, wid = tid >> 5;
    const int wm = wid & 3, wn = wid >> 2;          // 4 x 4 warp grid
    const int bz = blockIdx.z;
    const size_t aoff = (size_t)bz * sA, boff = (size_t)bz * sB, coff = (size_t)bz * sC;
    Ahi += aoff; Alo += aoff; Bhi += boff; Blo += boff;
    if (!HILO) Cf += coff; else { Chi += coff; Clo += coff; }
    const int m0 = blockIdx.y * 128, n0 = blockIdx.x * 256;

    const uint32_t sb = smem_u32(smem);

    float acc[2][8][4];
#pragma unroll
    for (int i = 0; i < 2; i++)
#pragma unroll
        for (int j = 0; j < 8; j++)
#pragma unroll
            for (int q = 0; q < 4; q++) acc[i][j][q] = 0.f;

    const int nk = K >> 5;

    // A tile layout: toffA(rt8,kt8) = (kt8*16 + rt8)*128   (128 rows -> 16 row-tiles)
    // B tile layout: toffB(rt8,kt8) = (kt8*32 + rt8)*128   (256 rows -> 32 row-tiles)
    const int s_row = tid >> 2, s_kt = tid & 3;
    const uint32_t a_off =
        (uint32_t)((s_kt * 16 + (s_row >> 3)) * 128 + (s_row & 7) * 16);
    const uint32_t b_off0 =
        (uint32_t)((s_kt * 32 + (s_row >> 3)) * 128 + (s_row & 7) * 16);
    const int s_row1 = s_row + 128;
    const uint32_t b_off1 =
        (uint32_t)((s_kt * 32 + (s_row1 >> 3)) * 128 + (s_row1 & 7) * 16);

    auto issue = [&](int i) {
        const uint32_t s = sb + (uint32_t)(i % NSTG) * STAGE;
        const int k0 = i << 5;
        const size_t ga  = (size_t)(m0 + s_row) * K + k0 + s_kt * 8;
        cp16(s + a_off,        Ahi + ga);
        cp16(s + 8192 + a_off, Alo + ga);
        const size_t gb0 = (size_t)(n0 + s_row)  * K + k0 + s_kt * 8;
        const size_t gb1 = (size_t)(n0 + s_row1) * K + k0 + s_kt * 8;
        cp16(s + 16384 + b_off0, Bhi + gb0);
        cp16(s + 16384 + b_off1, Bhi + gb1);
        cp16(s + 32768 + b_off0, Blo + gb0);
        cp16(s + 32768 + b_off1, Blo + gb1);
        asm volatile("cp.async.commit_group;");
    };

    issue(0);
    issue(1);
    const int mrow16 = (lane & 7) * 16;
    const int dm = (lane >> 3) & 1, dk = lane >> 4;         // A x4 decode
    const int sel_nt = lane >> 4, sel_k = (lane >> 3) & 1;  // B x4 decode

    for (int i = 0; i < nk; i++) {
        if (i == nk - 1) asm volatile("cp.async.wait_group 0;");
        else             asm volatile("cp.async.wait_group 1;");
        __syncthreads();
        if (i + 2 < nk) issue(i + 2);

        const uint32_t st   = sb + (uint32_t)(i % NSTG) * STAGE;
        const uint32_t sA_h = st;
        const uint32_t sA_l = st + 8192;
        const uint32_t sB_h = st + 16384;
        const uint32_t sB_l = st + 32768;

#pragma unroll
        for (int ks = 0; ks < 2; ks++) {
            // A fragments for both 16-row subtiles of this warp (32 rows)
            uint32_t ah[2][4], al[2][4];
#pragma unroll
            for (int mt = 0; mt < 2; mt++) {
                const int mt8 = wm * 4 + mt * 2 + dm;
                const uint32_t off =
                    (uint32_t)(((ks * 2 + dk) * 16 + mt8) * 128) + mrow16;
                ldm4(ah[mt], sA_h + off);
                ldm4(al[mt], sA_l + off);
            }
#pragma unroll
            for (int p = 0; p < 4; p++) {
                // B x4: two adjacent n-tiles, both k-subtiles
                const int nt8 = wn * 8 + p * 2;
                const uint32_t off =
                    (uint32_t)(((ks * 2 + sel_k) * 32 + nt8 + sel_nt) * 128) + mrow16;
                uint32_t bh[4], bl[4];
                ldm4(bh, sB_h + off);
                ldm4(bl, sB_l + off);
#pragma unroll
                for (int mt = 0; mt < 2; mt++) {
#pragma unroll
                    for (int e = 0; e < 2; e++) {
                        float* a0 = acc[mt][p * 2 + e];
                        mma16816(a0, ah[mt], bh + e * 2);
                        mma16816(a0, ah[mt], bl + e * 2);
                        mma16816(a0, al[mt], bh + e * 2);
                    }
                }
            }
        }
    }

    // ---------------- epilogue ----------------
    const int cq = (lane & 3) * 2, rq = lane >> 2;
#pragma unroll
    for (int nt = 0; nt < 8; nt++) {
        const int c = n0 + wn * 64 + nt * 8 + cq;
        float bv0 = 0.f, bv1 = 0.f;
        if (BIAS) { bv0 = bias[c]; bv1 = bias[c + 1]; }
        int mk0 = 1, mk1 = 1;
        if (MASK) {
            const int* mp = mask + (size_t)bz * N;
            mk0 = mp[c]; mk1 = mp[c + 1];
        }
#pragma unroll
        for (int mt = 0; mt < 2; mt++) {
            const int r0 = m0 + wm * 32 + mt * 16 + rq;
#pragma unroll
            for (int h = 0; h < 2; h++) {
                const int row = r0 + h * 8;
                float v0 = acc[mt][nt][h * 2 + 0] * alpha + bv0;
                float v1 = acc[mt][nt][h * 2 + 1] * alpha + bv1;
                if (MASK) { if (mk0 == 0) v0 = -1e9f; if (mk1 == 0) v1 = -1e9f; }
                if (RESID) {
                    float2 rv = *(const float2*)(resid + (size_t)row * N + c);
                    v0 += rv.x; v1 += rv.y;
                }
                if (RELU) { v0 = fmaxf(v0, 0.f); v1 = fmaxf(v1, 0.f); }
                if (HILO) {
                    __nv_bfloat16 h0 = __float2bfloat16(v0);
                    __nv_bfloat16 h1 = __float2bfloat16(v1);
                    *(__nv_bfloat162*)(Chi + (size_t)row * N + c) = __halves2bfloat162(h0, h1);
                    *(__nv_bfloat162*)(Clo + (size_t)row * N + c) =
                        __floats2bfloat162_rn(v0 - __bfloat162float(h0),
                                              v1 - __bfloat162float(h1));
                } else {
                    *(float2*)(Cf + (size_t)row * N + c) = make_float2(v0, v1);
                }
            }
        }
    }
}

// ---------------- LayerNorm -> bf16 hi/lo ----------------
__global__ void __launch_bounds__(256) ln_hilo(const float* __restrict__ x,
                                               const float* __restrict__ g,
                                               const float* __restrict__ b,
                                               __nv_bfloat16* __restrict__ oh,
                                               __nv_bfloat16* __restrict__ ol)
{
    size_t row = blockIdx.x;
    int t = threadIdx.x;
    float4 xv = ((const float4*)(x + row * ND))[t];
    float s  = xv.x + xv.y + xv.z + xv.w;
    float ss = xv.x*xv.x + xv.y*xv.y + xv.z*xv.z + xv.w*xv.w;
#pragma unroll
    for (int o = 16; o; o >>= 1) {
        s  += __shfl_xor_sync(0xffffffffu, s,  o);
        ss += __shfl_xor_sync(0xffffffffu, ss, o);
    }
    __shared__ float sh_s[8], sh_ss[8];
    if ((t & 31) == 0) { sh_s[t >> 5] = s; sh_ss[t >> 5] = ss; }
    __syncthreads();
    float ts = 0.f, tss = 0.f;
#pragma unroll
    for (int i = 0; i < 8; i++) { ts += sh_s[i]; tss += sh_ss[i]; }
    float mean = ts * (1.f / ND);
    float var  = tss * (1.f / ND) - mean * mean;
    float rstd = rsqrtf(var + 1e-5f);
    float4 gv = ((const float4*)g)[t];
    float4 bv = ((const float4*)b)[t];
    float o0 = (xv.x - mean) * rstd * gv.x + bv.x;
    float o1 = (xv.y - mean) * rstd * gv.y + bv.y;
    float o2 = (xv.z - mean) * rstd * gv.z + bv.z;
    float o3 = (xv.w - mean) * rstd * gv.w + bv.w;
    __nv_bfloat16 h0 = __float2bfloat16(o0), h1 = __float2bfloat16(o1);
    __nv_bfloat16 h2 = __float2bfloat16(o2), h3 = __float2bfloat16(o3);
    __nv_bfloat162* ph = (__nv_bfloat162*)(oh + row * ND);
    __nv_bfloat162* pl = (__nv_bfloat162*)(ol + row * ND);
    ph[2*t]   = __halves2bfloat162(h0, h1);
    ph[2*t+1] = __halves2bfloat162(h2, h3);
    pl[2*t]   = __floats2bfloat162_rn(o0 - __bfloat162float(h0), o1 - __bfloat162float(h1));
    pl[2*t+1] = __floats2bfloat162_rn(o2 - __bfloat162float(h2), o3 - __bfloat162float(h3));
}

// ---------------- softmax (in-place fp32) + bf16 hi/lo ----------------
__global__ void __launch_bounds__(256) softmax_hilo(float* __restrict__ w,
                                                    __nv_bfloat16* __restrict__ oh,
                                                    __nv_bfloat16* __restrict__ ol)
{
    float* p = w + (size_t)blockIdx.x * NS;
    int t = threadIdx.x;
    float4 v0 = ((const float4*)p)[t];
    float4 v1 = ((const float4*)p)[t + 256];
    float mx = fmaxf(fmaxf(fmaxf(v0.x, v0.y), fmaxf(v0.z, v0.w)),
                     fmaxf(fmaxf(v1.x, v1.y), fmaxf(v1.z, v1.w)));
#pragma unroll
    for (int o = 16; o; o >>= 1) mx = fmaxf(mx, __shfl_xor_sync(0xffffffffu, mx, o));
    __shared__ float shm[8], shs[8];
    if ((t & 31) == 0) shm[t >> 5] = mx;
    __syncthreads();
    mx = shm[0];
#pragma unroll
    for (int i = 1; i < 8; i++) mx = fmaxf(mx, shm[i]);
    float e[8];
    e[0] = __expf(v0.x - mx); e[1] = __expf(v0.y - mx);
    e[2] = __expf(v0.z - mx); e[3] = __expf(v0.w - mx);
    e[4] = __expf(v1.x - mx); e[5] = __expf(v1.y - mx);
    e[6] = __expf(v1.z - mx); e[7] = __expf(v1.w - mx);
    float s = e[0]+e[1]+e[2]+e[3]+e[4]+e[5]+e[6]+e[7];
#pragma unroll
    for (int o = 16; o; o >>= 1) s += __shfl_xor_sync(0xffffffffu, s, o);
    if ((t & 31) == 0) shs[t >> 5] = s;
    __syncthreads();
    s = 0.f;
#pragma unroll
    for (int i = 0; i < 8; i++) s += shs[i];
    float inv = 1.f / s;
#pragma unroll
    for (int i = 0; i < 8; i++) e[i] *= inv;
    ((float4*)p)[t]       = make_float4(e[0], e[1], e[2], e[3]);
    ((float4*)p)[t + 256] = make_float4(e[4], e[5], e[6], e[7]);

    __nv_bfloat162* ph = (__nv_bfloat162*)(oh + (size_t)blockIdx.x * NS);
    __nv_bfloat162* pl = (__nv_bfloat162*)(ol + (size_t)blockIdx.x * NS);
#pragma unroll
    for (int q = 0; q < 2; q++) {
        int base = q ? 512 : 0;
        int ei = q * 4;
        __nv_bfloat16 h0 = __float2bfloat16(e[ei+0]);
        __nv_bfloat16 h1 = __float2bfloat16(e[ei+1]);
        __nv_bfloat16 h2 = __float2bfloat16(e[ei+2]);
        __nv_bfloat16 h3 = __float2bfloat16(e[ei+3]);
        ph[base + 2*t]   = __halves2bfloat162(h0, h1);
        ph[base + 2*t+1] = __halves2bfloat162(h2, h3);
        pl[base + 2*t]   = __floats2bfloat162_rn(e[ei+0] - __bfloat162float(h0),
                                                 e[ei+1] - __bfloat162float(h1));
        pl[base + 2*t+1] = __floats2bfloat162_rn(e[ei+2] - __bfloat162float(h2),
                                                 e[ei+3] - __bfloat162float(h3));
    }
}

// ---------------- weight transpose + split ----------------
__global__ void __launch_bounds__(256) wt_conv(const float* __restrict__ W,
                                               __nv_bfloat16* __restrict__ Th,
                                               __nv_bfloat16* __restrict__ Tl)
{
    __shared__ float tile[64][65];
    int k0 = blockIdx.y * 64, n0 = blockIdx.x * 64;
#pragma unroll
    for (int u = threadIdx.x; u < 4096; u += 256) {
        int r = u >> 6, c = u & 63;
        tile[r][c] = W[(size_t)(k0 + r) * ND + n0 + c];
    }
    __syncthreads();
#pragma unroll
    for (int u = threadIdx.x; u < 4096; u += 256) {
        int r = u >> 6, c = u & 63;
        float v = tile[c][r];
        __nv_bfloat16 h = __float2bfloat16(v);
        Th[(size_t)(n0 + r) * ND + k0 + c] = h;
        Tl[(size_t)(n0 + r) * ND + k0 + c] = __float2bfloat16(v - __bfloat162float(h));
    }
}

// ---------------- bf16 transpose (k -> kT per batch) ----------------
__global__ void __launch_bounds__(256) kt_kernel(const __nv_bfloat16* __restrict__ ih,
                                                 const __nv_bfloat16* __restrict__ il,
                                                 __nv_bfloat16* __restrict__ oh,
                                                 __nv_bfloat16* __restrict__ ol)
{
    __shared__ __nv_bfloat16 th[64][65], tl[64][65];
    int b = blockIdx.z;
    int d0 = blockIdx.x * 64, s0 = blockIdx.y * 64;
    const size_t ib = (size_t)b * NS * ND;
    const size_t ob = (size_t)b * ND * NS;
#pragma unroll
    for (int u = threadIdx.x; u < 4096; u += 256) {
        int r = u >> 6, c = u & 63;
        th[r][c] = ih[ib + (size_t)(s0 + r) * ND + d0 + c];
        tl[r][c] = il[ib + (size_t)(s0 + r) * ND + d0 + c];
    }
    __syncthreads();
#pragma unroll
    for (int u = threadIdx.x; u < 4096; u += 256) {
        int r = u >> 6, c = u & 63;
        oh[ob + (size_t)(d0 + r) * NS + s0 + c] = th[c][r];
        ol[ob + (size_t)(d0 + r) * NS + s0 + c] = tl[c][r];
    }
}

// ---------------- driver ----------------
extern "C" void kernel_launch(void* const* d_in, const int* in_sizes, int n_in,
                              void* d_out, int out_size)
{
    const float* x    = (const float*)d_in[0];
    const int*   mask = (const int*)  d_in[1];
    const float* ln1g = (const float*)d_in[2];
    const float* ln1b = (const float*)d_in[3];
    const float* Wq   = (const float*)d_in[4];
    const float* bq   = (const float*)d_in[5];
    const float* Wk   = (const float*)d_in[6];
    const float* bk   = (const float*)d_in[7];
    const float* Wo   = (const float*)d_in[8];
    const float* bo   = (const float*)d_in[9];
    const float* ln2g = (const float*)d_in[10];
    const float* ln2b = (const float*)d_in[11];
    const float* W1   = (const float*)d_in[12];
    const float* b1   = (const float*)d_in[13];
    const float* W2   = (const float*)d_in[14];
    const float* b2   = (const float*)d_in[15];

    float* out  = (float*)d_out;
    float* wout = out + (size_t)NROWS * ND;

    __nv_bfloat16 *xn_h, *xn_l, *q_h, *q_l, *k_h, *k_l, *kT_h, *kT_l;
    __nv_bfloat16 *w_h, *w_l, *at_h, *at_l, *xn2_h, *xn2_l, *h_h, *h_l, *wt;
    float* x2;
    cudaGetSymbolAddress((void**)&xn_h, g_xn_h);   cudaGetSymbolAddress((void**)&xn_l, g_xn_l);
    cudaGetSymbolAddress((void**)&q_h,  g_q_h);    cudaGetSymbolAddress((void**)&q_l,  g_q_l);
    cudaGetSymbolAddress((void**)&k_h,  g_k_h);    cudaGetSymbolAddress((void**)&k_l,  g_k_l);
    cudaGetSymbolAddress((void**)&kT_h, g_kT_h);   cudaGetSymbolAddress((void**)&kT_l, g_kT_l);
    cudaGetSymbolAddress((void**)&w_h,  g_w_h);    cudaGetSymbolAddress((void**)&w_l,  g_w_l);
    cudaGetSymbolAddress((void**)&at_h, g_at_h);   cudaGetSymbolAddress((void**)&at_l, g_at_l);
    cudaGetSymbolAddress((void**)&xn2_h,g_xn2_h);  cudaGetSymbolAddress((void**)&xn2_l,g_xn2_l);
    cudaGetSymbolAddress((void**)&h_h,  g_h_h);    cudaGetSymbolAddress((void**)&h_l,  g_h_l);
    cudaGetSymbolAddress((void**)&x2,   g_x2);
    cudaGetSymbolAddress((void**)&wt,   g_wt);

    __nv_bfloat16 *wq_h = wt + 0*2*WSZ, *wq_l = wt + 0*2*WSZ + WSZ;
    __nv_bfloat16 *wk_h = wt + 1*2*WSZ, *wk_l = wt + 1*2*WSZ + WSZ;
    __nv_bfloat16 *wo_h = wt + 2*2*WSZ, *wo_l = wt + 2*2*WSZ + WSZ;
    __nv_bfloat16 *w1_h = wt + 3*2*WSZ, *w1_l = wt + 3*2*WSZ + WSZ;
    __nv_bfloat16 *w2_h = wt + 4*2*WSZ, *w2_l = wt + 4*2*WSZ + WSZ;

    cudaFuncSetAttribute(gemm_tc<true,false,false,false,true>,
                         cudaFuncAttributeMaxDynamicSharedMemorySize, SMEMSZ);
    cudaFuncSetAttribute(gemm_tc<false,false,true,false,false>,
                         cudaFuncAttributeMaxDynamicSharedMemorySize, SMEMSZ);
    cudaFuncSetAttribute(gemm_tc<false,false,false,false,true>,
                         cudaFuncAttributeMaxDynamicSharedMemorySize, SMEMSZ);
    cudaFuncSetAttribute(gemm_tc<true,false,false,true,false>,
                         cudaFuncAttributeMaxDynamicSharedMemorySize, SMEMSZ);
    cudaFuncSetAttribute(gemm_tc<true,true,false,false,true>,
                         cudaFuncAttributeMaxDynamicSharedMemorySize, SMEMSZ);

    dim3 gW(16, 16);
    wt_conv<<<gW, 256>>>(Wq, wq_h, wq_l);
    wt_conv<<<gW, 256>>>(Wk, wk_h, wk_l);
    wt_conv<<<gW, 256>>>(Wo, wo_h, wo_l);
    wt_conv<<<gW, 256>>>(W1, w1_h, w1_l);
    wt_conv<<<gW, 256>>>(W2, w2_h, w2_l);

    // 1) xn = LN1(x)
    ln_hilo<<<NROWS, 256>>>(x, ln1g, ln1b, xn_h, xn_l);

    dim3 gP(ND / 256, NROWS / 128, 1);
    // 2) q, k projections (v == k, faithful reference bug)
    gemm_tc<true,false,false,false,true><<<gP, 512, SMEMSZ>>>(
        xn_h, xn_l, wq_h, wq_l, NROWS, ND, ND, 0, 0, 0,
        nullptr, q_h, q_l, bq, nullptr, nullptr, 1.f);
    gemm_tc<true,false,false,false,true><<<gP, 512, SMEMSZ>>>(
        xn_h, xn_l, wk_h, wk_l, NROWS, ND, ND, 0, 0, 0,
        nullptr, k_h, k_l, bk, nullptr, nullptr, 1.f);

    // 3) kT for attn@v
    kt_kernel<<<dim3(ND / 64, NS / 64, NB), 256>>>(k_h, k_l, kT_h, kT_l);

    // 4) scores = (q @ k^T)/32, masked -> wout (fp32)
    dim3 gS(NS / 256, NS / 128, NB);
    gemm_tc<false,false,true,false,false><<<gS, 512, SMEMSZ>>>(
        q_h, q_l, k_h, k_l, NS, NS, ND,
        (long long)NS * ND, (long long)NS * ND, (long long)NS * NS,
        wout, nullptr, nullptr, nullptr, nullptr, mask, 0.03125f);

    // 5) softmax in place + hi/lo
    softmax_hilo<<<NROWS, 256>>>(wout, w_h, w_l);

    // 6) attn = w @ v  (v == k)
    dim3 gA(ND / 256, NS / 128, NB);
    gemm_tc<false,false,false,false,true><<<gA, 512, SMEMSZ>>>(
        w_h, w_l, kT_h, kT_l, NS, ND, NS,
        (long long)NS * NS, (long long)ND * NS, (long long)NS * ND,
        nullptr, at_h, at_l, nullptr, nullptr, nullptr, 1.f);

    // 7) x2 = x + attn @ Wo + bo
    gemm_tc<true,false,false,true,false><<<gP, 512, SMEMSZ>>>(
        at_h, at_l, wo_h, wo_l, NROWS, ND, ND, 0, 0, 0,
        x2, nullptr, nullptr, bo, x, nullptr, 1.f);

    // 8) xn2 = LN2(x2)
    ln_hilo<<<NROWS, 256>>>(x2, ln2g, ln2b, xn2_h, xn2_l);

    // 9) h = relu(xn2 @ W1 + b1)
    gemm_tc<true,true,false,false,true><<<gP, 512, SMEMSZ>>>(
        xn2_h, xn2_l, w1_h, w1_l, NROWS, ND, ND, 0, 0, 0,
        nullptr, h_h, h_l, b1, nullptr, nullptr, 1.f);

    // 10) out = x2 + h @ W2 + b2
    gemm_tc<true,false,false,true,false><<<gP, 512, SMEMSZ>>>(
        h_h, h_l, w2_h, w2_l, NROWS, ND, ND, 0, 0, 0,
        out, nullptr, nullptr, b2, x2, nullptr, 1.f);
}

// round 6
// speedup vs baseline: 1.5174x; 1.4848x over previous
#include <cuda_runtime.h>
#include <cuda_fp16.h>
#include <stdint.h>

#define NB 8
#define NS 2048
#define ND 1024
#define NROWS (NB * NS)          // 16384
#define WSZ ((size_t)ND * ND)

// ---------------- scratch (no cudaMalloc allowed) ----------------
__device__ __half g_xn  [(size_t)NROWS * ND];
__device__ __half g_q   [(size_t)NROWS * ND];
__device__ __half g_k_h [(size_t)NROWS * ND], g_k_l [(size_t)NROWS * ND];
__device__ __half g_kT_h[(size_t)NROWS * ND], g_kT_l[(size_t)NROWS * ND];
__device__ __half g_w   [(size_t)NB * NS * NS];
__device__ __half g_at  [(size_t)NROWS * ND];
__device__ float  g_x2  [(size_t)NROWS * ND];
__device__ __half g_xn2 [(size_t)NROWS * ND];
__device__ __half g_h   [(size_t)NROWS * ND];
__device__ __half g_wt  [5 * 2 * WSZ];   // 5 transposed weights, hi+lo

// ---------------- helpers ----------------
__device__ __forceinline__ uint32_t smem_u32(const void* p) {
    uint32_t a;
    asm("{ .reg .u64 t; cvta.to.shared.u64 t, %1; cvt.u32.u64 %0, t; }" : "=r"(a) : "l"(p));
    return a;
}
__device__ __forceinline__ void cp16(uint32_t dst, const void* src) {
    asm volatile("cp.async.cg.shared.global [%0], [%1], 16;" :: "r"(dst), "l"(src));
}
__device__ __forceinline__ void ldmA(uint32_t* a, uint32_t addr) {
    asm volatile("ldmatrix.sync.aligned.m8n8.x4.shared.b16 {%0,%1,%2,%3}, [%4];"
                 : "=r"(a[0]), "=r"(a[1]), "=r"(a[2]), "=r"(a[3]) : "r"(addr));
}
__device__ __forceinline__ void ldmB(uint32_t* b, uint32_t addr) {
    asm volatile("ldmatrix.sync.aligned.m8n8.x2.shared.b16 {%0,%1}, [%2];"
                 : "=r"(b[0]), "=r"(b[1]) : "r"(addr));
}
__device__ __forceinline__ void mma16816(float* c, const uint32_t* a, const uint32_t* b) {
    asm volatile("mma.sync.aligned.m16n8k16.row.col.f32.f16.f16.f32 "
                 "{%0,%1,%2,%3}, {%4,%5,%6,%7}, {%8,%9}, {%0,%1,%2,%3};"
                 : "+f"(c[0]), "+f"(c[1]), "+f"(c[2]), "+f"(c[3])
                 : "r"(a[0]), "r"(a[1]), "r"(a[2]), "r"(a[3]), "r"(b[0]), "r"(b[1]));
}

// smem stage: A 8K | B_h 8K | B_l 8K = 24KB; 3 stages = 72KB
#define STAGE  24576
#define NSTG   3
#define SMEMSZ (NSTG * STAGE)
// tile offset inside an 8K operand block: 8x8 fp16 tiles, id = kt8*16 + rt8
__device__ __forceinline__ uint32_t toff(int rt8, int kt8) {
    return (uint32_t)((kt8 * 16 + rt8) * 128);
}

// ---------------- warp-MMA 2-pass fp16 GEMM: 128x128 CTA tile, kchunk 32 ----------------
// D = alpha * A[M,K](fp16) * (Bhi+Blo)[N,K]^T  (+bias) (mask==0 -> -1e9) (+resid) (relu)
// OUT: 0 = fp32, 1 = fp16 single, 2 = fp16 hi/lo split
template <bool BIAS, bool RELU, bool MASK, bool RESID, int OUT>
__global__ void __launch_bounds__(256, 2) gemm_tc(
    const __half* __restrict__ A,
    const __half* __restrict__ Bhi, const __half* __restrict__ Blo,
    int M, int N, int K,
    long long sA, long long sB, long long sC,
    float* __restrict__ Cf,
    __half* __restrict__ Chi, __half* __restrict__ Clo,
    const float* __restrict__ bias,
    const float* __restrict__ resid,
    const int* __restrict__ mask,
    float alpha)
{
    extern __shared__ char smem[];
    const int tid  = threadIdx.x;
    const int lane = tid & 31, wid = tid >> 5;
    const int wm = wid & 1, wn = wid >> 1;          // 2 x 4 warp grid, warp tile 64x32
    const int bz = blockIdx.z;
    const size_t aoff = (size_t)bz * sA, boff = (size_t)bz * sB, coff = (size_t)bz * sC;
    A += aoff; Bhi += boff; Blo += boff;
    if (OUT == 0) Cf += coff; else { Chi += coff; if (OUT == 2) Clo += coff; }
    const int m0 = blockIdx.y * 128, n0 = blockIdx.x * 128;

    const uint32_t sb = smem_u32(smem);

    float acc[4][4][4];
#pragma unroll
    for (int i = 0; i < 4; i++)
#pragma unroll
        for (int j = 0; j < 4; j++)
#pragma unroll
            for (int q = 0; q < 4; q++) acc[i][j][q] = 0.f;

    const int nk = K >> 5;

    // staging map: idx = tid + h*256 -> row = idx>>2, kt8 = idx&3
    const int r_lo = tid >> 2, kt = tid & 3;
    const uint32_t d_lo = (uint32_t)((kt * 16 + (r_lo >> 3)) * 128 + (r_lo & 7) * 16);
    const int r_hi = r_lo + 64;
    const uint32_t d_hi = (uint32_t)((kt * 16 + (r_hi >> 3)) * 128 + (r_hi & 7) * 16);

    auto issue = [&](int i) {
        const uint32_t s = sb + (uint32_t)(i % NSTG) * STAGE;
        const int k0 = i << 5;
        const size_t ga_lo = (size_t)(m0 + r_lo) * K + k0 + kt * 8;
        const size_t ga_hi = (size_t)(m0 + r_hi) * K + k0 + kt * 8;
        const size_t gb_lo = (size_t)(n0 + r_lo) * K + k0 + kt * 8;
        const size_t gb_hi = (size_t)(n0 + r_hi) * K + k0 + kt * 8;
        cp16(s + d_lo,         A   + ga_lo);
        cp16(s + d_hi,         A   + ga_hi);
        cp16(s +  8192 + d_lo, Bhi + gb_lo);
        cp16(s +  8192 + d_hi, Bhi + gb_hi);
        cp16(s + 16384 + d_lo, Blo + gb_lo);
        cp16(s + 16384 + d_hi, Blo + gb_hi);
        asm volatile("cp.async.commit_group;");
    };

    issue(0);
    issue(1);
    const int mrow16 = (lane & 7) * 16;

    for (int i = 0; i < nk; i++) {
        if (i == nk - 1) asm volatile("cp.async.wait_group 0;");
        else             asm volatile("cp.async.wait_group 1;");
        __syncthreads();
        if (i + 2 < nk) issue(i + 2);

        const uint32_t st   = sb + (uint32_t)(i % NSTG) * STAGE;
        const uint32_t sA   = st;
        const uint32_t sB_h = st + 8192;
        const uint32_t sB_l = st + 16384;

#pragma unroll
        for (int ks = 0; ks < 2; ks++) {
            uint32_t bh[4][2], bl[4][2];
            const int bmi = (lane >> 3) & 1;
#pragma unroll
            for (int nt = 0; nt < 4; nt++) {
                const int nt8 = wn * 4 + nt;
                const uint32_t off = toff(nt8, ks * 2 + bmi) + mrow16;
                ldmB(bh[nt], sB_h + off);
                ldmB(bl[nt], sB_l + off);
            }
            const int mi = lane >> 3;
            const int dm = mi & 1, dk = mi >> 1;
#pragma unroll
            for (int mt = 0; mt < 4; mt++) {
                const int mt8 = wm * 8 + mt * 2 + dm;
                const uint32_t off = toff(mt8, ks * 2 + dk) + mrow16;
                uint32_t a[4];
                ldmA(a, sA + off);
#pragma unroll
                for (int nt = 0; nt < 4; nt++) {
                    mma16816(acc[mt][nt], a, bh[nt]);
                    mma16816(acc[mt][nt], a, bl[nt]);
                }
            }
        }
    }

    // ---------------- epilogue ----------------
    const int cq = (lane & 3) * 2, rq = lane >> 2;
#pragma unroll
    for (int nt = 0; nt < 4; nt++) {
        const int c = n0 + wn * 32 + nt * 8 + cq;
        float bv0 = 0.f, bv1 = 0.f;
        if (BIAS) { bv0 = bias[c]; bv1 = bias[c + 1]; }
        int mk0 = 1, mk1 = 1;
        if (MASK) {
            const int* mp = mask + (size_t)bz * N;
            mk0 = mp[c]; mk1 = mp[c + 1];
        }
#pragma unroll
        for (int mt = 0; mt < 4; mt++) {
            const int r0 = m0 + wm * 64 + mt * 16 + rq;
#pragma unroll
            for (int h = 0; h < 2; h++) {
                const int row = r0 + h * 8;
                float v0 = acc[mt][nt][h * 2 + 0] * alpha + bv0;
                float v1 = acc[mt][nt][h * 2 + 1] * alpha + bv1;
                if (MASK) { if (mk0 == 0) v0 = -1e9f; if (mk1 == 0) v1 = -1e9f; }
                if (RESID) {
                    float2 rv = *(const float2*)(resid + (size_t)row * N + c);
                    v0 += rv.x; v1 += rv.y;
                }
                if (RELU) { v0 = fmaxf(v0, 0.f); v1 = fmaxf(v1, 0.f); }
                if (OUT == 0) {
                    *(float2*)(Cf + (size_t)row * N + c) = make_float2(v0, v1);
                } else if (OUT == 1) {
                    *(__half2*)(Chi + (size_t)row * N + c) =
                        __halves2half2(__float2half(v0), __float2half(v1));
                } else {
                    __half h0 = __float2half(v0);
                    __half h1 = __float2half(v1);
                    *(__half2*)(Chi + (size_t)row * N + c) = __halves2half2(h0, h1);
                    *(__half2*)(Clo + (size_t)row * N + c) =
                        __floats2half2_rn(v0 - __half2float(h0), v1 - __half2float(h1));
                }
            }
        }
    }
}

// ---------------- LayerNorm -> fp16 ----------------
__global__ void __launch_bounds__(256) ln_f16(const float* __restrict__ x,
                                              const float* __restrict__ g,
                                              const float* __restrict__ b,
                                              __half* __restrict__ o)
{
    size_t row = blockIdx.x;
    int t = threadIdx.x;
    float4 xv = ((const float4*)(x + row * ND))[t];
    float s  = xv.x + xv.y + xv.z + xv.w;
    float ss = xv.x*xv.x + xv.y*xv.y + xv.z*xv.z + xv.w*xv.w;
#pragma unroll
    for (int off = 16; off; off >>= 1) {
        s  += __shfl_xor_sync(0xffffffffu, s,  off);
        ss += __shfl_xor_sync(0xffffffffu, ss, off);
    }
    __shared__ float sh_s[8], sh_ss[8];
    if ((t & 31) == 0) { sh_s[t >> 5] = s; sh_ss[t >> 5] = ss; }
    __syncthreads();
    float ts = 0.f, tss = 0.f;
#pragma unroll
    for (int i = 0; i < 8; i++) { ts += sh_s[i]; tss += sh_ss[i]; }
    float mean = ts * (1.f / ND);
    float var  = tss * (1.f / ND) - mean * mean;
    float rstd = rsqrtf(var + 1e-5f);
    float4 gv = ((const float4*)g)[t];
    float4 bv = ((const float4*)b)[t];
    float o0 = (xv.x - mean) * rstd * gv.x + bv.x;
    float o1 = (xv.y - mean) * rstd * gv.y + bv.y;
    float o2 = (xv.z - mean) * rstd * gv.z + bv.z;
    float o3 = (xv.w - mean) * rstd * gv.w + bv.w;
    __half2* ph = (__half2*)(o + row * ND);
    ph[2*t]   = __halves2half2(__float2half(o0), __float2half(o1));
    ph[2*t+1] = __halves2half2(__float2half(o2), __float2half(o3));
}

// ---------------- softmax (fp32 in-place) + fp16 emission ----------------
__global__ void __launch_bounds__(256) softmax_f16(float* __restrict__ w,
                                                   __half* __restrict__ o)
{
    float* p = w + (size_t)blockIdx.x * NS;
    int t = threadIdx.x;
    float4 v0 = ((const float4*)p)[t];
    float4 v1 = ((const float4*)p)[t + 256];
    float mx = fmaxf(fmaxf(fmaxf(v0.x, v0.y), fmaxf(v0.z, v0.w)),
                     fmaxf(fmaxf(v1.x, v1.y), fmaxf(v1.z, v1.w)));
#pragma unroll
    for (int off = 16; off; off >>= 1) mx = fmaxf(mx, __shfl_xor_sync(0xffffffffu, mx, off));
    __shared__ float shm[8], shs[8];
    if ((t & 31) == 0) shm[t >> 5] = mx;
    __syncthreads();
    mx = shm[0];
#pragma unroll
    for (int i = 1; i < 8; i++) mx = fmaxf(mx, shm[i]);
    float e[8];
    e[0] = __expf(v0.x - mx); e[1] = __expf(v0.y - mx);
    e[2] = __expf(v0.z - mx); e[3] = __expf(v0.w - mx);
    e[4] = __expf(v1.x - mx); e[5] = __expf(v1.y - mx);
    e[6] = __expf(v1.z - mx); e[7] = __expf(v1.w - mx);
    float s = e[0]+e[1]+e[2]+e[3]+e[4]+e[5]+e[6]+e[7];
#pragma unroll
    for (int off = 16; off; off >>= 1) s += __shfl_xor_sync(0xffffffffu, s, off);
    if ((t & 31) == 0) shs[t >> 5] = s;
    __syncthreads();
    s = 0.f;
#pragma unroll
    for (int i = 0; i < 8; i++) s += shs[i];
    float inv = 1.f / s;
#pragma unroll
    for (int i = 0; i < 8; i++) e[i] *= inv;
    ((float4*)p)[t]       = make_float4(e[0], e[1], e[2], e[3]);
    ((float4*)p)[t + 256] = make_float4(e[4], e[5], e[6], e[7]);

    __half2* ph = (__half2*)(o + (size_t)blockIdx.x * NS);
    ph[2*t]       = __halves2half2(__float2half(e[0]), __float2half(e[1]));
    ph[2*t+1]     = __halves2half2(__float2half(e[2]), __float2half(e[3]));
    ph[512 + 2*t]   = __halves2half2(__float2half(e[4]), __float2half(e[5]));
    ph[512 + 2*t+1] = __halves2half2(__float2half(e[6]), __float2half(e[7]));
}

// ---------------- weight transpose + split: W[K,N] fp32 -> WT[N,K] fp16 hi/lo ----------------
__global__ void __launch_bounds__(256) wt_conv(const float* __restrict__ W,
                                               __half* __restrict__ Th,
                                               __half* __restrict__ Tl)
{
    __shared__ float tile[64][65];
    int k0 = blockIdx.y * 64, n0 = blockIdx.x * 64;
#pragma unroll
    for (int u = threadIdx.x; u < 4096; u += 256) {
        int r = u >> 6, c = u & 63;
        tile[r][c] = W[(size_t)(k0 + r) * ND + n0 + c];
    }
    __syncthreads();
#pragma unroll
    for (int u = threadIdx.x; u < 4096; u += 256) {
        int r = u >> 6, c = u & 63;
        float v = tile[c][r];
        __half h = __float2half(v);
        Th[(size_t)(n0 + r) * ND + k0 + c] = h;
        Tl[(size_t)(n0 + r) * ND + k0 + c] = __float2half(v - __half2float(h));
    }
}

// ---------------- fp16 transpose (k -> kT per batch, hi+lo) ----------------
__global__ void __launch_bounds__(256) kt_kernel(const __half* __restrict__ ih,
                                                 const __half* __restrict__ il,
                                                 __half* __restrict__ oh,
                                                 __half* __restrict__ ol)
{
    __shared__ __half th[64][65], tl[64][65];
    int b = blockIdx.z;
    int d0 = blockIdx.x * 64, s0 = blockIdx.y * 64;
    const size_t ib = (size_t)b * NS * ND;
    const size_t ob = (size_t)b * ND * NS;
#pragma unroll
    for (int u = threadIdx.x; u < 4096; u += 256) {
        int r = u >> 6, c = u & 63;
        th[r][c] = ih[ib + (size_t)(s0 + r) * ND + d0 + c];
        tl[r][c] = il[ib + (size_t)(s0 + r) * ND + d0 + c];
    }
    __syncthreads();
#pragma unroll
    for (int u = threadIdx.x; u < 4096; u += 256) {
        int r = u >> 6, c = u & 63;
        oh[ob + (size_t)(d0 + r) * NS + s0 + c] = th[c][r];
        ol[ob + (size_t)(d0 + r) * NS + s0 + c] = tl[c][r];
    }
}

// ---------------- driver ----------------
extern "C" void kernel_launch(void* const* d_in, const int* in_sizes, int n_in,
                              void* d_out, int out_size)
{
    const float* x    = (const float*)d_in[0];
    const int*   mask = (const int*)  d_in[1];
    const float* ln1g = (const float*)d_in[2];
    const float* ln1b = (const float*)d_in[3];
    const float* Wq   = (const float*)d_in[4];
    const float* bq   = (const float*)d_in[5];
    const float* Wk   = (const float*)d_in[6];
    const float* bk   = (const float*)d_in[7];
    const float* Wo   = (const float*)d_in[8];
    const float* bo   = (const float*)d_in[9];
    const float* ln2g = (const float*)d_in[10];
    const float* ln2b = (const float*)d_in[11];
    const float* W1   = (const float*)d_in[12];
    const float* b1   = (const float*)d_in[13];
    const float* W2   = (const float*)d_in[14];
    const float* b2   = (const float*)d_in[15];

    float* out  = (float*)d_out;
    float* wout = out + (size_t)NROWS * ND;

    __half *xn, *q, *k_h, *k_l, *kT_h, *kT_l, *w, *at, *xn2, *h, *wt;
    float* x2;
    cudaGetSymbolAddress((void**)&xn,   g_xn);
    cudaGetSymbolAddress((void**)&q,    g_q);
    cudaGetSymbolAddress((void**)&k_h,  g_k_h);   cudaGetSymbolAddress((void**)&k_l,  g_k_l);
    cudaGetSymbolAddress((void**)&kT_h, g_kT_h);  cudaGetSymbolAddress((void**)&kT_l, g_kT_l);
    cudaGetSymbolAddress((void**)&w,    g_w);
    cudaGetSymbolAddress((void**)&at,   g_at);
    cudaGetSymbolAddress((void**)&xn2,  g_xn2);
    cudaGetSymbolAddress((void**)&h,    g_h);
    cudaGetSymbolAddress((void**)&x2,   g_x2);
    cudaGetSymbolAddress((void**)&wt,   g_wt);

    __half *wq_h = wt + 0*2*WSZ, *wq_l = wt + 0*2*WSZ + WSZ;
    __half *wk_h = wt + 1*2*WSZ, *wk_l = wt + 1*2*WSZ + WSZ;
    __half *wo_h = wt + 2*2*WSZ, *wo_l = wt + 2*2*WSZ + WSZ;
    __half *w1_h = wt + 3*2*WSZ, *w1_l = wt + 3*2*WSZ + WSZ;
    __half *w2_h = wt + 4*2*WSZ, *w2_l = wt + 4*2*WSZ + WSZ;

    cudaFuncSetAttribute(gemm_tc<true,false,false,false,1>,
                         cudaFuncAttributeMaxDynamicSharedMemorySize, SMEMSZ);
    cudaFuncSetAttribute(gemm_tc<true,false,false,false,2>,
                         cudaFuncAttributeMaxDynamicSharedMemorySize, SMEMSZ);
    cudaFuncSetAttribute(gemm_tc<false,false,true,false,0>,
                         cudaFuncAttributeMaxDynamicSharedMemorySize, SMEMSZ);
    cudaFuncSetAttribute(gemm_tc<false,false,false,false,1>,
                         cudaFuncAttributeMaxDynamicSharedMemorySize, SMEMSZ);
    cudaFuncSetAttribute(gemm_tc<true,false,false,true,0>,
                         cudaFuncAttributeMaxDynamicSharedMemorySize, SMEMSZ);
    cudaFuncSetAttribute(gemm_tc<true,true,false,false,1>,
                         cudaFuncAttributeMaxDynamicSharedMemorySize, SMEMSZ);

    dim3 gW(16, 16);
    wt_conv<<<gW, 256>>>(Wq, wq_h, wq_l);
    wt_conv<<<gW, 256>>>(Wk, wk_h, wk_l);
    wt_conv<<<gW, 256>>>(Wo, wo_h, wo_l);
    wt_conv<<<gW, 256>>>(W1, w1_h, w1_l);
    wt_conv<<<gW, 256>>>(W2, w2_h, w2_l);

    // 1) xn = LN1(x)
    ln_f16<<<NROWS, 256>>>(x, ln1g, ln1b, xn);

    dim3 gP(ND / 128, NROWS / 128, 1);
    // 2) q = xn@Wq+bq (fp16 out); k = xn@Wk+bk (fp16 hi/lo out)  (v == k, faithful bug)
    gemm_tc<true,false,false,false,1><<<gP, 256, SMEMSZ>>>(
        xn, wq_h, wq_l, NROWS, ND, ND, 0, 0, 0,
        nullptr, q, nullptr, bq, nullptr, nullptr, 1.f);
    gemm_tc<true,false,false,false,2><<<gP, 256, SMEMSZ>>>(
        xn, wk_h, wk_l, NROWS, ND, ND, 0, 0, 0,
        nullptr, k_h, k_l, bk, nullptr, nullptr, 1.f);

    // 3) kT (hi/lo) for attn@v
    kt_kernel<<<dim3(ND / 64, NS / 64, NB), 256>>>(k_h, k_l, kT_h, kT_l);

    // 4) scores = (q @ k^T)/32, masked -> wout (fp32)
    dim3 gS(NS / 128, NS / 128, NB);
    gemm_tc<false,false,true,false,0><<<gS, 256, SMEMSZ>>>(
        q, k_h, k_l, NS, NS, ND,
        (long long)NS * ND, (long long)NS * ND, (long long)NS * NS,
        wout, nullptr, nullptr, nullptr, nullptr, mask, 0.03125f);

    // 5) softmax in place + fp16 w
    softmax_f16<<<NROWS, 256>>>(wout, w);

    // 6) attn = w @ v  (v == k)
    dim3 gA(ND / 128, NS / 128, NB);
    gemm_tc<false,false,false,false,1><<<gA, 256, SMEMSZ>>>(
        w, kT_h, kT_l, NS, ND, NS,
        (long long)NS * NS, (long long)ND * NS, (long long)NS * ND,
        nullptr, at, nullptr, nullptr, nullptr, nullptr, 1.f);

    // 7) x2 = x + attn @ Wo + bo
    gemm_tc<true,false,false,true,0><<<gP, 256, SMEMSZ>>>(
        at, wo_h, wo_l, NROWS, ND, ND, 0, 0, 0,
        x2, nullptr, nullptr, bo, x, nullptr, 1.f);

    // 8) xn2 = LN2(x2)
    ln_f16<<<NROWS, 256>>>(x2, ln2g, ln2b, xn2);

    // 9) h = relu(xn2 @ W1 + b1)
    gemm_tc<true,true,false,false,1><<<gP, 256, SMEMSZ>>>(
        xn2, w1_h, w1_l, NROWS, ND, ND, 0, 0, 0,
        nullptr, h, nullptr, b1, nullptr, nullptr, 1.f);

    // 10) out = x2 + h @ W2 + b2
    gemm_tc<true,false,false,true,0><<<gP, 256, SMEMSZ>>>(
        h, w2_h, w2_l, NROWS, ND, ND, 0, 0, 0,
        out, nullptr, nullptr, b2, x2, nullptr, 1.f);
}

// round 7
// speedup vs baseline: 1.7625x; 1.1615x over previous
#include <cuda_runtime.h>
#include <cuda_fp16.h>
#include <stdint.h>

#define NB 8
#define NS 2048
#define ND 1024
#define NROWS (NB * NS)          // 16384
#define WSZ ((size_t)ND * ND)

// ---------------- scratch (no cudaMalloc allowed) ----------------
__device__ __half g_xn  [(size_t)NROWS * ND];
__device__ __half g_q   [(size_t)NROWS * ND];
__device__ __half g_k   [(size_t)NROWS * ND];
__device__ __half g_kT  [(size_t)NROWS * ND];
__device__ __half g_w   [(size_t)NB * NS * NS];
__device__ __half g_at  [(size_t)NROWS * ND];
__device__ float  g_x2  [(size_t)NROWS * ND];
__device__ __half g_xn2 [(size_t)NROWS * ND];
__device__ __half g_h   [(size_t)NROWS * ND];
__device__ __half g_wt  [5 * 2 * WSZ];   // 5 transposed weights, hi+lo

// ---------------- helpers ----------------
__device__ __forceinline__ uint32_t smem_u32(const void* p) {
    uint32_t a;
    asm("{ .reg .u64 t; cvta.to.shared.u64 t, %1; cvt.u32.u64 %0, t; }" : "=r"(a) : "l"(p));
    return a;
}
__device__ __forceinline__ void cp16(uint32_t dst, const void* src) {
    asm volatile("cp.async.cg.shared.global [%0], [%1], 16;" :: "r"(dst), "l"(src));
}
__device__ __forceinline__ void ldmA(uint32_t* a, uint32_t addr) {
    asm volatile("ldmatrix.sync.aligned.m8n8.x4.shared.b16 {%0,%1,%2,%3}, [%4];"
                 : "=r"(a[0]), "=r"(a[1]), "=r"(a[2]), "=r"(a[3]) : "r"(addr));
}
__device__ __forceinline__ void ldmB(uint32_t* b, uint32_t addr) {
    asm volatile("ldmatrix.sync.aligned.m8n8.x2.shared.b16 {%0,%1}, [%2];"
                 : "=r"(b[0]), "=r"(b[1]) : "r"(addr));
}
__device__ __forceinline__ void mma16816(float* c, const uint32_t* a, const uint32_t* b) {
    asm volatile("mma.sync.aligned.m16n8k16.row.col.f32.f16.f16.f32 "
                 "{%0,%1,%2,%3}, {%4,%5,%6,%7}, {%8,%9}, {%0,%1,%2,%3};"
                 : "+f"(c[0]), "+f"(c[1]), "+f"(c[2]), "+f"(c[3])
                 : "r"(a[0]), "r"(a[1]), "r"(a[2]), "r"(a[3]), "r"(b[0]), "r"(b[1]));
}

#define NSTG 3
// tile offset inside an 8K operand block: 8x8 fp16 tiles, id = kt8*16 + rt8
__device__ __forceinline__ uint32_t toff(int rt8, int kt8) {
    return (uint32_t)((kt8 * 16 + rt8) * 128);
}

// ---------------- warp-MMA fp16 GEMM: 128x128 CTA tile, kchunk 32 ----------------
// D = alpha * A[M,K](fp16) * B[N,K]^T  (+bias) (mask==0 -> -1e9) (+resid) (relu)
// PASS2: B = Bhi + Blo split (2 MMA passes).  OUT: 0 = fp32, 1 = fp16
template <bool BIAS, bool RELU, bool MASK, bool RESID, bool PASS2, int OUT>
__global__ void __launch_bounds__(256, 2) gemm_tc(
    const __half* __restrict__ A,
    const __half* __restrict__ Bhi, const __half* __restrict__ Blo,
    int M, int N, int K,
    long long sA, long long sB, long long sC,
    float* __restrict__ Cf,
    __half* __restrict__ Ch,
    const float* __restrict__ bias,
    const float* __restrict__ resid,
    const int* __restrict__ mask,
    float alpha)
{
    constexpr uint32_t STAGE = PASS2 ? 24576u : 16384u;
    extern __shared__ char smem[];
    const int tid  = threadIdx.x;
    const int lane = tid & 31, wid = tid >> 5;
    const int wm = wid & 1, wn = wid >> 1;          // 2 x 4 warp grid, warp tile 64x32
    const int bz = blockIdx.z;
    const size_t aoff = (size_t)bz * sA, boff = (size_t)bz * sB, coff = (size_t)bz * sC;
    A += aoff; Bhi += boff; if (PASS2) Blo += boff;
    if (OUT == 0) Cf += coff; else Ch += coff;
    const int m0 = blockIdx.y * 128, n0 = blockIdx.x * 128;

    const uint32_t sb = smem_u32(smem);

    float acc[4][4][4];
#pragma unroll
    for (int i = 0; i < 4; i++)
#pragma unroll
        for (int j = 0; j < 4; j++)
#pragma unroll
            for (int q = 0; q < 4; q++) acc[i][j][q] = 0.f;

    const int nk = K >> 5;

    // staging map: idx -> row = idx>>2, kt8 = idx&3 (8x8 tiles contiguous 128B)
    const int r_lo = tid >> 2, kt = tid & 3;
    const uint32_t d_lo = (uint32_t)((kt * 16 + (r_lo >> 3)) * 128 + (r_lo & 7) * 16);
    const int r_hi = r_lo + 64;
    const uint32_t d_hi = (uint32_t)((kt * 16 + (r_hi >> 3)) * 128 + (r_hi & 7) * 16);

    auto issue = [&](int i) {
        const uint32_t s = sb + (uint32_t)(i % NSTG) * STAGE;
        const int k0 = i << 5;
        const size_t ga_lo = (size_t)(m0 + r_lo) * K + k0 + kt * 8;
        const size_t ga_hi = (size_t)(m0 + r_hi) * K + k0 + kt * 8;
        const size_t gb_lo = (size_t)(n0 + r_lo) * K + k0 + kt * 8;
        const size_t gb_hi = (size_t)(n0 + r_hi) * K + k0 + kt * 8;
        cp16(s + d_lo,        A   + ga_lo);
        cp16(s + d_hi,        A   + ga_hi);
        cp16(s + 8192 + d_lo, Bhi + gb_lo);
        cp16(s + 8192 + d_hi, Bhi + gb_hi);
        if (PASS2) {
            cp16(s + 16384 + d_lo, Blo + gb_lo);
            cp16(s + 16384 + d_hi, Blo + gb_hi);
        }
        asm volatile("cp.async.commit_group;");
    };

    issue(0);
    issue(1);
    const int mrow16 = (lane & 7) * 16;
    const int bmi = (lane >> 3) & 1;                 // B x2 k-subtile select
    const int dm = (lane >> 3) & 1, dk = lane >> 4;  // A x4 decode

    for (int i = 0; i < nk; i++) {
        if (i == nk - 1) asm volatile("cp.async.wait_group 0;");
        else             asm volatile("cp.async.wait_group 1;");
        __syncthreads();
        if (i + 2 < nk) issue(i + 2);

        const uint32_t st   = sb + (uint32_t)(i % NSTG) * STAGE;
        const uint32_t sAa  = st;
        const uint32_t sB_h = st + 8192;
        const uint32_t sB_l = st + 16384;

#pragma unroll
        for (int ks = 0; ks < 2; ks++) {
            // load ALL fragments for this k-subtile first (max ILP in MMA sweeps)
            uint32_t a[4][4];
#pragma unroll
            for (int mt = 0; mt < 4; mt++) {
                const int mt8 = wm * 8 + mt * 2 + dm;
                ldmA(a[mt], sAa + toff(mt8, ks * 2 + dk) + mrow16);
            }
            uint32_t bh[4][2];
#pragma unroll
            for (int nt = 0; nt < 4; nt++)
                ldmB(bh[nt], sB_h + toff(wn * 4 + nt, ks * 2 + bmi) + mrow16);
            uint32_t bl[4][2];
            if (PASS2) {
#pragma unroll
                for (int nt = 0; nt < 4; nt++)
                    ldmB(bl[nt], sB_l + toff(wn * 4 + nt, ks * 2 + bmi) + mrow16);
            }
            // pass hi: 16 independent accumulators back-to-back
#pragma unroll
            for (int mt = 0; mt < 4; mt++)
#pragma unroll
                for (int nt = 0; nt < 4; nt++)
                    mma16816(acc[mt][nt], a[mt], bh[nt]);
            if (PASS2) {
#pragma unroll
                for (int mt = 0; mt < 4; mt++)
#pragma unroll
                    for (int nt = 0; nt < 4; nt++)
                        mma16816(acc[mt][nt], a[mt], bl[nt]);
            }
        }
    }

    // ---------------- epilogue ----------------
    const int cq = (lane & 3) * 2, rq = lane >> 2;
#pragma unroll
    for (int nt = 0; nt < 4; nt++) {
        const int c = n0 + wn * 32 + nt * 8 + cq;
        float bv0 = 0.f, bv1 = 0.f;
        if (BIAS) { bv0 = bias[c]; bv1 = bias[c + 1]; }
        int mk0 = 1, mk1 = 1;
        if (MASK) {
            const int* mp = mask + (size_t)bz * N;
            mk0 = mp[c]; mk1 = mp[c + 1];
        }
#pragma unroll
        for (int mt = 0; mt < 4; mt++) {
            const int r0 = m0 + wm * 64 + mt * 16 + rq;
#pragma unroll
            for (int h = 0; h < 2; h++) {
                const int row = r0 + h * 8;
                float v0 = acc[mt][nt][h * 2 + 0] * alpha + bv0;
                float v1 = acc[mt][nt][h * 2 + 1] * alpha + bv1;
                if (MASK) { if (mk0 == 0) v0 = -1e9f; if (mk1 == 0) v1 = -1e9f; }
                if (RESID) {
                    float2 rv = *(const float2*)(resid + (size_t)row * N + c);
                    v0 += rv.x; v1 += rv.y;
                }
                if (RELU) { v0 = fmaxf(v0, 0.f); v1 = fmaxf(v1, 0.f); }
                if (OUT == 0) {
                    *(float2*)(Cf + (size_t)row * N + c) = make_float2(v0, v1);
                } else {
                    *(__half2*)(Ch + (size_t)row * N + c) =
                        __halves2half2(__float2half(v0), __float2half(v1));
                }
            }
        }
    }
}

// ---------------- LayerNorm -> fp16 ----------------
__global__ void __launch_bounds__(256) ln_f16(const float* __restrict__ x,
                                              const float* __restrict__ g,
                                              const float* __restrict__ b,
                                              __half* __restrict__ o)
{
    size_t row = blockIdx.x;
    int t = threadIdx.x;
    float4 xv = ((const float4*)(x + row * ND))[t];
    float s  = xv.x + xv.y + xv.z + xv.w;
    float ss = xv.x*xv.x + xv.y*xv.y + xv.z*xv.z + xv.w*xv.w;
#pragma unroll
    for (int off = 16; off; off >>= 1) {
        s  += __shfl_xor_sync(0xffffffffu, s,  off);
        ss += __shfl_xor_sync(0xffffffffu, ss, off);
    }
    __shared__ float sh_s[8], sh_ss[8];
    if ((t & 31) == 0) { sh_s[t >> 5] = s; sh_ss[t >> 5] = ss; }
    __syncthreads();
    float ts = 0.f, tss = 0.f;
#pragma unroll
    for (int i = 0; i < 8; i++) { ts += sh_s[i]; tss += sh_ss[i]; }
    float mean = ts * (1.f / ND);
    float var  = tss * (1.f / ND) - mean * mean;
    float rstd = rsqrtf(var + 1e-5f);
    float4 gv = ((const float4*)g)[t];
    float4 bv = ((const float4*)b)[t];
    float o0 = (xv.x - mean) * rstd * gv.x + bv.x;
    float o1 = (xv.y - mean) * rstd * gv.y + bv.y;
    float o2 = (xv.z - mean) * rstd * gv.z + bv.z;
    float o3 = (xv.w - mean) * rstd * gv.w + bv.w;
    __half2* ph = (__half2*)(o + row * ND);
    ph[2*t]   = __halves2half2(__float2half(o0), __float2half(o1));
    ph[2*t+1] = __halves2half2(__float2half(o2), __float2half(o3));
}

// ---------------- softmax (fp32 in-place) + fp16 emission ----------------
__global__ void __launch_bounds__(256) softmax_f16(float* __restrict__ w,
                                                   __half* __restrict__ o)
{
    float* p = w + (size_t)blockIdx.x * NS;
    int t = threadIdx.x;
    float4 v0 = ((const float4*)p)[t];
    float4 v1 = ((const float4*)p)[t + 256];
    float mx = fmaxf(fmaxf(fmaxf(v0.x, v0.y), fmaxf(v0.z, v0.w)),
                     fmaxf(fmaxf(v1.x, v1.y), fmaxf(v1.z, v1.w)));
#pragma unroll
    for (int off = 16; off; off >>= 1) mx = fmaxf(mx, __shfl_xor_sync(0xffffffffu, mx, off));
    __shared__ float shm[8], shs[8];
    if ((t & 31) == 0) shm[t >> 5] = mx;
    __syncthreads();
    mx = shm[0];
#pragma unroll
    for (int i = 1; i < 8; i++) mx = fmaxf(mx, shm[i]);
    float e[8];
    e[0] = __expf(v0.x - mx); e[1] = __expf(v0.y - mx);
    e[2] = __expf(v0.z - mx); e[3] = __expf(v0.w - mx);
    e[4] = __expf(v1.x - mx); e[5] = __expf(v1.y - mx);
    e[6] = __expf(v1.z - mx); e[7] = __expf(v1.w - mx);
    float s = e[0]+e[1]+e[2]+e[3]+e[4]+e[5]+e[6]+e[7];
#pragma unroll
    for (int off = 16; off; off >>= 1) s += __shfl_xor_sync(0xffffffffu, s, off);
    if ((t & 31) == 0) shs[t >> 5] = s;
    __syncthreads();
    s = 0.f;
#pragma unroll
    for (int i = 0; i < 8; i++) s += shs[i];
    float inv = 1.f / s;
#pragma unroll
    for (int i = 0; i < 8; i++) e[i] *= inv;
    ((float4*)p)[t]       = make_float4(e[0], e[1], e[2], e[3]);
    ((float4*)p)[t + 256] = make_float4(e[4], e[5], e[6], e[7]);

    __half2* ph = (__half2*)(o + (size_t)blockIdx.x * NS);
    ph[2*t]         = __halves2half2(__float2half(e[0]), __float2half(e[1]));
    ph[2*t+1]       = __halves2half2(__float2half(e[2]), __float2half(e[3]));
    ph[512 + 2*t]   = __halves2half2(__float2half(e[4]), __float2half(e[5]));
    ph[512 + 2*t+1] = __halves2half2(__float2half(e[6]), __float2half(e[7]));
}

// ---------------- weight transpose + split: W[K,N] fp32 -> WT[N,K] fp16 hi/lo ----------------
__global__ void __launch_bounds__(256) wt_conv(const float* __restrict__ W,
                                               __half* __restrict__ Th,
                                               __half* __restrict__ Tl)
{
    __shared__ float tile[64][65];
    int k0 = blockIdx.y * 64, n0 = blockIdx.x * 64;
#pragma unroll
    for (int u = threadIdx.x; u < 4096; u += 256) {
        int r = u >> 6, c = u & 63;
        tile[r][c] = W[(size_t)(k0 + r) * ND + n0 + c];
    }
    __syncthreads();
#pragma unroll
    for (int u = threadIdx.x; u < 4096; u += 256) {
        int r = u >> 6, c = u & 63;
        float v = tile[c][r];
        __half h = __float2half(v);
        Th[(size_t)(n0 + r) * ND + k0 + c] = h;
        Tl[(size_t)(n0 + r) * ND + k0 + c] = __float2half(v - __half2float(h));
    }
}

// ---------------- fp16 transpose (k -> kT per batch) ----------------
__global__ void __launch_bounds__(256) kt_kernel(const __half* __restrict__ ih,
                                                 __half* __restrict__ oh)
{
    __shared__ __half th[64][65];
    int b = blockIdx.z;
    int d0 = blockIdx.x * 64, s0 = blockIdx.y * 64;
    const size_t ib = (size_t)b * NS * ND;
    const size_t ob = (size_t)b * ND * NS;
#pragma unroll
    for (int u = threadIdx.x; u < 4096; u += 256) {
        int r = u >> 6, c = u & 63;
        th[r][c] = ih[ib + (size_t)(s0 + r) * ND + d0 + c];
    }
    __syncthreads();
#pragma unroll
    for (int u = threadIdx.x; u < 4096; u += 256) {
        int r = u >> 6, c = u & 63;
        oh[ob + (size_t)(d0 + r) * NS + s0 + c] = th[c][r];
    }
}

// ---------------- driver ----------------
extern "C" void kernel_launch(void* const* d_in, const int* in_sizes, int n_in,
                              void* d_out, int out_size)
{
    const float* x    = (const float*)d_in[0];
    const int*   mask = (const int*)  d_in[1];
    const float* ln1g = (const float*)d_in[2];
    const float* ln1b = (const float*)d_in[3];
    const float* Wq   = (const float*)d_in[4];
    const float* bq   = (const float*)d_in[5];
    const float* Wk   = (const float*)d_in[6];
    const float* bk   = (const float*)d_in[7];
    const float* Wo   = (const float*)d_in[8];
    const float* bo   = (const float*)d_in[9];
    const float* ln2g = (const float*)d_in[10];
    const float* ln2b = (const float*)d_in[11];
    const float* W1   = (const float*)d_in[12];
    const float* b1   = (const float*)d_in[13];
    const float* W2   = (const float*)d_in[14];
    const float* b2   = (const float*)d_in[15];

    float* out  = (float*)d_out;
    float* wout = out + (size_t)NROWS * ND;

    __half *xn, *q, *k, *kT, *w, *at, *xn2, *h, *wt;
    float* x2;
    cudaGetSymbolAddress((void**)&xn,  g_xn);
    cudaGetSymbolAddress((void**)&q,   g_q);
    cudaGetSymbolAddress((void**)&k,   g_k);
    cudaGetSymbolAddress((void**)&kT,  g_kT);
    cudaGetSymbolAddress((void**)&w,   g_w);
    cudaGetSymbolAddress((void**)&at,  g_at);
    cudaGetSymbolAddress((void**)&xn2, g_xn2);
    cudaGetSymbolAddress((void**)&h,   g_h);
    cudaGetSymbolAddress((void**)&x2,  g_x2);
    cudaGetSymbolAddress((void**)&wt,  g_wt);

    __half *wq_h = wt + 0*2*WSZ, *wq_l = wt + 0*2*WSZ + WSZ;
    __half *wk_h = wt + 1*2*WSZ, *wk_l = wt + 1*2*WSZ + WSZ;
    __half *wo_h = wt + 2*2*WSZ, *wo_l = wt + 2*2*WSZ + WSZ;
    __half *w1_h = wt + 3*2*WSZ, *w1_l = wt + 3*2*WSZ + WSZ;
    __half *w2_h = wt + 4*2*WSZ, *w2_l = wt + 4*2*WSZ + WSZ;

    const int SM2 = NSTG * 24576;   // 2-pass stages
    const int SM1 = NSTG * 16384;   // 1-pass stages

    cudaFuncSetAttribute(gemm_tc<true,false,false,false,true,1>,
                         cudaFuncAttributeMaxDynamicSharedMemorySize, SM2);
    cudaFuncSetAttribute(gemm_tc<false,false,true,false,false,0>,
                         cudaFuncAttributeMaxDynamicSharedMemorySize, SM1);
    cudaFuncSetAttribute(gemm_tc<false,false,false,false,false,1>,
                         cudaFuncAttributeMaxDynamicSharedMemorySize, SM1);
    cudaFuncSetAttribute(gemm_tc<true,false,false,true,true,0>,
                         cudaFuncAttributeMaxDynamicSharedMemorySize, SM2);
    cudaFuncSetAttribute(gemm_tc<true,true,false,false,true,1>,
                         cudaFuncAttributeMaxDynamicSharedMemorySize, SM2);

    dim3 gW(16, 16);
    wt_conv<<<gW, 256>>>(Wq, wq_h, wq_l);
    wt_conv<<<gW, 256>>>(Wk, wk_h, wk_l);
    wt_conv<<<gW, 256>>>(Wo, wo_h, wo_l);
    wt_conv<<<gW, 256>>>(W1, w1_h, w1_l);
    wt_conv<<<gW, 256>>>(W2, w2_h, w2_l);

    // 1) xn = LN1(x)
    ln_f16<<<NROWS, 256>>>(x, ln1g, ln1b, xn);

    dim3 gP(ND / 128, NROWS / 128, 1);
    // 2) q = xn@Wq+bq ; k = xn@Wk+bk  (both fp16 single; v == k, faithful bug)
    gemm_tc<true,false,false,false,true,1><<<gP, 256, SM2>>>(
        xn, wq_h, wq_l, NROWS, ND, ND, 0, 0, 0,
        nullptr, q, bq, nullptr, nullptr, 1.f);
    gemm_tc<true,false,false,false,true,1><<<gP, 256, SM2>>>(
        xn, wk_h, wk_l, NROWS, ND, ND, 0, 0, 0,
        nullptr, k, bk, nullptr, nullptr, 1.f);

    // 3) kT for attn@v
    kt_kernel<<<dim3(ND / 64, NS / 64, NB), 256>>>(k, kT);

    // 4) scores = (q @ k^T)/32, masked -> wout (fp32), 1-pass
    dim3 gS(NS / 128, NS / 128, NB);
    gemm_tc<false,false,true,false,false,0><<<gS, 256, SM1>>>(
        q, k, nullptr, NS, NS, ND,
        (long long)NS * ND, (long long)NS * ND, (long long)NS * NS,
        wout, nullptr, nullptr, nullptr, mask, 0.03125f);

    // 5) softmax in place + fp16 w
    softmax_f16<<<NROWS, 256>>>(wout, w);

    // 6) attn = w @ v  (v == k), 1-pass
    dim3 gA(ND / 128, NS / 128, NB);
    gemm_tc<false,false,false,false,false,1><<<gA, 256, SM1>>>(
        w, kT, nullptr, NS, ND, NS,
        (long long)NS * NS, (long long)ND * NS, (long long)NS * ND,
        nullptr, at, nullptr, nullptr, nullptr, 1.f);

    // 7) x2 = x + attn @ Wo + bo
    gemm_tc<true,false,false,true,true,0><<<gP, 256, SM2>>>(
        at, wo_h, wo_l, NROWS, ND, ND, 0, 0, 0,
        x2, nullptr, bo, x, nullptr, 1.f);

    // 8) xn2 = LN2(x2)
    ln_f16<<<NROWS, 256>>>(x2, ln2g, ln2b, xn2);

    // 9) h = relu(xn2 @ W1 + b1)
    gemm_tc<true,true,false,false,true,1><<<gP, 256, SM2>>>(
        xn2, w1_h, w1_l, NROWS, ND, ND, 0, 0, 0,
        nullptr, h, b1, nullptr, nullptr, 1.f);

    // 10) out = x2 + h @ W2 + b2
    gemm_tc<true,false,false,true,true,0><<<gP, 256, SM2>>>(
        h, w2_h, w2_l, NROWS, ND, ND, 0, 0, 0,
        out, nullptr, b2, x2, nullptr, 1.f);
}

// round 8
// speedup vs baseline: 2.0441x; 1.1598x over previous
#include <cuda_runtime.h>
#include <cuda_fp16.h>
#include <stdint.h>

#define NB 8
#define NS 2048
#define ND 1024
#define NROWS (NB * NS)          // 16384
#define WSZ ((size_t)ND * ND)

// ---------------- scratch (no cudaMalloc allowed) ----------------
__device__ __half g_xn  [(size_t)NROWS * ND];
__device__ __half g_q   [(size_t)NROWS * ND];
__device__ __half g_k   [(size_t)NROWS * ND];
__device__ __half g_kT  [(size_t)NROWS * ND];
__device__ __half g_w   [(size_t)NB * NS * NS];
__device__ __half g_at  [(size_t)NROWS * ND];
__device__ float  g_x2  [(size_t)NROWS * ND];
__device__ __half g_xn2 [(size_t)NROWS * ND];
__device__ __half g_h   [(size_t)NROWS * ND];
__device__ __half g_wt  [5 * 2 * WSZ];   // 5 transposed weights, hi+lo

// ---------------- helpers ----------------
__device__ __forceinline__ uint32_t smem_u32(const void* p) {
    uint32_t a;
    asm("{ .reg .u64 t; cvta.to.shared.u64 t, %1; cvt.u32.u64 %0, t; }" : "=r"(a) : "l"(p));
    return a;
}
__device__ __forceinline__ void cp16(uint32_t dst, const void* src) {
    asm volatile("cp.async.cg.shared.global [%0], [%1], 16;" :: "r"(dst), "l"(src));
}
__device__ __forceinline__ void ldmA(uint32_t* a, uint32_t addr) {
    asm volatile("ldmatrix.sync.aligned.m8n8.x4.shared.b16 {%0,%1,%2,%3}, [%4];"
                 : "=r"(a[0]), "=r"(a[1]), "=r"(a[2]), "=r"(a[3]) : "r"(addr));
}
__device__ __forceinline__ void ldmB(uint32_t* b, uint32_t addr) {
    asm volatile("ldmatrix.sync.aligned.m8n8.x2.shared.b16 {%0,%1}, [%2];"
                 : "=r"(b[0]), "=r"(b[1]) : "r"(addr));
}
__device__ __forceinline__ void mma16816(float* c, const uint32_t* a, const uint32_t* b) {
    asm volatile("mma.sync.aligned.m16n8k16.row.col.f32.f16.f16.f32 "
                 "{%0,%1,%2,%3}, {%4,%5,%6,%7}, {%8,%9}, {%0,%1,%2,%3};"
                 : "+f"(c[0]), "+f"(c[1]), "+f"(c[2]), "+f"(c[3])
                 : "r"(a[0]), "r"(a[1]), "r"(a[2]), "r"(a[3]), "r"(b[0]), "r"(b[1]));
}

#define NSTG 3
// tile offset inside an 8K operand block: 8x8 fp16 tiles, id = kt8*16 + rt8
__device__ __forceinline__ uint32_t toff(int rt8, int kt8) {
    return (uint32_t)((kt8 * 16 + rt8) * 128);
}

// ---------------- warp-MMA fp16 GEMM: 128x128 CTA tile, kchunk 32 ----------------
// D = alpha * A[M,K](fp16) * B[N,K]^T  (+bias) (mask==0 -> -1e9) (+resid) (relu)
// PASS2: B = Bhi + Blo split (2 MMA passes).  OUT: 0 = fp32, 1 = fp16
template <bool BIAS, bool RELU, bool MASK, bool RESID, bool PASS2, int OUT>
__global__ void __launch_bounds__(256, 2) gemm_tc(
    const __half* __restrict__ A,
    const __half* __restrict__ Bhi, const __half* __restrict__ Blo,
    int M, int N, int K,
    long long sA, long long sB, long long sC,
    float* __restrict__ Cf,
    __half* __restrict__ Ch,
    const float* __restrict__ bias,
    const float* __restrict__ resid,
    const int* __restrict__ mask,
    float alpha)
{
    constexpr uint32_t STAGE = PASS2 ? 24576u : 16384u;
    extern __shared__ char smem[];
    const int tid  = threadIdx.x;
    const int lane = tid & 31, wid = tid >> 5;
    const int wm = wid & 1, wn = wid >> 1;          // 2 x 4 warp grid, warp tile 64x32
    const int bz = blockIdx.z;
    const size_t aoff = (size_t)bz * sA, boff = (size_t)bz * sB, coff = (size_t)bz * sC;
    A += aoff; Bhi += boff; if (PASS2) Blo += boff;
    if (OUT == 0) Cf += coff; else Ch += coff;
    const int m0 = blockIdx.y * 128, n0 = blockIdx.x * 128;

    const uint32_t sb = smem_u32(smem);

    float acc[4][4][4];
#pragma unroll
    for (int i = 0; i < 4; i++)
#pragma unroll
        for (int j = 0; j < 4; j++)
#pragma unroll
            for (int q = 0; q < 4; q++) acc[i][j][q] = 0.f;

    const int nk = K >> 5;

    // staging map: idx -> row = idx>>2, kt8 = idx&3 (8x8 tiles contiguous 128B)
    const int r_lo = tid >> 2, kt = tid & 3;
    const uint32_t d_lo = (uint32_t)((kt * 16 + (r_lo >> 3)) * 128 + (r_lo & 7) * 16);
    const int r_hi = r_lo + 64;
    const uint32_t d_hi = (uint32_t)((kt * 16 + (r_hi >> 3)) * 128 + (r_hi & 7) * 16);

    auto issue = [&](int i) {
        const uint32_t s = sb + (uint32_t)(i % NSTG) * STAGE;
        const int k0 = i << 5;
        const size_t ga_lo = (size_t)(m0 + r_lo) * K + k0 + kt * 8;
        const size_t ga_hi = (size_t)(m0 + r_hi) * K + k0 + kt * 8;
        const size_t gb_lo = (size_t)(n0 + r_lo) * K + k0 + kt * 8;
        const size_t gb_hi = (size_t)(n0 + r_hi) * K + k0 + kt * 8;
        cp16(s + d_lo,        A   + ga_lo);
        cp16(s + d_hi,        A   + ga_hi);
        cp16(s + 8192 + d_lo, Bhi + gb_lo);
        cp16(s + 8192 + d_hi, Bhi + gb_hi);
        if (PASS2) {
            cp16(s + 16384 + d_lo, Blo + gb_lo);
            cp16(s + 16384 + d_hi, Blo + gb_hi);
        }
        asm volatile("cp.async.commit_group;");
    };

    issue(0);
    issue(1);
    const int mrow16 = (lane & 7) * 16;
    const int bmi = (lane >> 3) & 1;                 // B x2 k-subtile select
    const int dm = (lane >> 3) & 1, dk = lane >> 4;  // A x4 decode

    for (int i = 0; i < nk; i++) {
        if (i == nk - 1) asm volatile("cp.async.wait_group 0;");
        else             asm volatile("cp.async.wait_group 1;");
        __syncthreads();
        if (i + 2 < nk) issue(i + 2);

        const uint32_t st   = sb + (uint32_t)(i % NSTG) * STAGE;
        const uint32_t sAa  = st;
        const uint32_t sB_h = st + 8192;
        const uint32_t sB_l = st + 16384;

#pragma unroll
        for (int ks = 0; ks < 2; ks++) {
            // load ALL fragments for this k-subtile first (max ILP in MMA sweeps)
            uint32_t a[4][4];
#pragma unroll
            for (int mt = 0; mt < 4; mt++) {
                const int mt8 = wm * 8 + mt * 2 + dm;
                ldmA(a[mt], sAa + toff(mt8, ks * 2 + dk) + mrow16);
            }
            uint32_t bh[4][2];
#pragma unroll
            for (int nt = 0; nt < 4; nt++)
                ldmB(bh[nt], sB_h + toff(wn * 4 + nt, ks * 2 + bmi) + mrow16);
            uint32_t bl[4][2];
            if (PASS2) {
#pragma unroll
                for (int nt = 0; nt < 4; nt++)
                    ldmB(bl[nt], sB_l + toff(wn * 4 + nt, ks * 2 + bmi) + mrow16);
            }
            // pass hi: 16 independent accumulators back-to-back
#pragma unroll
            for (int mt = 0; mt < 4; mt++)
#pragma unroll
                for (int nt = 0; nt < 4; nt++)
                    mma16816(acc[mt][nt], a[mt], bh[nt]);
            if (PASS2) {
#pragma unroll
                for (int mt = 0; mt < 4; mt++)
#pragma unroll
                    for (int nt = 0; nt < 4; nt++)
                        mma16816(acc[mt][nt], a[mt], bl[nt]);
            }
        }
    }

    // ---------------- epilogue ----------------
    const int cq = (lane & 3) * 2, rq = lane >> 2;
#pragma unroll
    for (int nt = 0; nt < 4; nt++) {
        const int c = n0 + wn * 32 + nt * 8 + cq;
        float bv0 = 0.f, bv1 = 0.f;
        if (BIAS) { bv0 = bias[c]; bv1 = bias[c + 1]; }
        int mk0 = 1, mk1 = 1;
        if (MASK) {
            const int* mp = mask + (size_t)bz * N;
            mk0 = mp[c]; mk1 = mp[c + 1];
        }
#pragma unroll
        for (int mt = 0; mt < 4; mt++) {
            const int r0 = m0 + wm * 64 + mt * 16 + rq;
#pragma unroll
            for (int h = 0; h < 2; h++) {
                const int row = r0 + h * 8;
                float v0 = acc[mt][nt][h * 2 + 0] * alpha + bv0;
                float v1 = acc[mt][nt][h * 2 + 1] * alpha + bv1;
                if (MASK) { if (mk0 == 0) v0 = -1e9f; if (mk1 == 0) v1 = -1e9f; }
                if (RESID) {
                    float2 rv = *(const float2*)(resid + (size_t)row * N + c);
                    v0 += rv.x; v1 += rv.y;
                }
                if (RELU) { v0 = fmaxf(v0, 0.f); v1 = fmaxf(v1, 0.f); }
                if (OUT == 0) {
                    *(float2*)(Cf + (size_t)row * N + c) = make_float2(v0, v1);
                } else {
                    *(__half2*)(Ch + (size_t)row * N + c) =
                        __halves2half2(__float2half(v0), __float2half(v1));
                }
            }
        }
    }
}

// ---------------- LayerNorm -> fp16 ----------------
__global__ void __launch_bounds__(256) ln_f16(const float* __restrict__ x,
                                              const float* __restrict__ g,
                                              const float* __restrict__ b,
                                              __half* __restrict__ o)
{
    size_t row = blockIdx.x;
    int t = threadIdx.x;
    float4 xv = ((const float4*)(x + row * ND))[t];
    float s  = xv.x + xv.y + xv.z + xv.w;
    float ss = xv.x*xv.x + xv.y*xv.y + xv.z*xv.z + xv.w*xv.w;
#pragma unroll
    for (int off = 16; off; off >>= 1) {
        s  += __shfl_xor_sync(0xffffffffu, s,  off);
        ss += __shfl_xor_sync(0xffffffffu, ss, off);
    }
    __shared__ float sh_s[8], sh_ss[8];
    if ((t & 31) == 0) { sh_s[t >> 5] = s; sh_ss[t >> 5] = ss; }
    __syncthreads();
    float ts = 0.f, tss = 0.f;
#pragma unroll
    for (int i = 0; i < 8; i++) { ts += sh_s[i]; tss += sh_ss[i]; }
    float mean = ts * (1.f / ND);
    float var  = tss * (1.f / ND) - mean * mean;
    float rstd = rsqrtf(var + 1e-5f);
    float4 gv = ((const float4*)g)[t];
    float4 bv = ((const float4*)b)[t];
    float o0 = (xv.x - mean) * rstd * gv.x + bv.x;
    float o1 = (xv.y - mean) * rstd * gv.y + bv.y;
    float o2 = (xv.z - mean) * rstd * gv.z + bv.z;
    float o3 = (xv.w - mean) * rstd * gv.w + bv.w;
    __half2* ph = (__half2*)(o + row * ND);
    ph[2*t]   = __halves2half2(__float2half(o0), __float2half(o1));
    ph[2*t+1] = __halves2half2(__float2half(o2), __float2half(o3));
}

// ---------------- softmax (fp32 in-place) + fp16 emission ----------------
__global__ void __launch_bounds__(256) softmax_f16(float* __restrict__ w,
                                                   __half* __restrict__ o)
{
    float* p = w + (size_t)blockIdx.x * NS;
    int t = threadIdx.x;
    float4 v0 = ((const float4*)p)[t];
    float4 v1 = ((const float4*)p)[t + 256];
    float mx = fmaxf(fmaxf(fmaxf(v0.x, v0.y), fmaxf(v0.z, v0.w)),
                     fmaxf(fmaxf(v1.x, v1.y), fmaxf(v1.z, v1.w)));
#pragma unroll
    for (int off = 16; off; off >>= 1) mx = fmaxf(mx, __shfl_xor_sync(0xffffffffu, mx, off));
    __shared__ float shm[8], shs[8];
    if ((t & 31) == 0) shm[t >> 5] = mx;
    __syncthreads();
    mx = shm[0];
#pragma unroll
    for (int i = 1; i < 8; i++) mx = fmaxf(mx, shm[i]);
    float e[8];
    e[0] = __expf(v0.x - mx); e[1] = __expf(v0.y - mx);
    e[2] = __expf(v0.z - mx); e[3] = __expf(v0.w - mx);
    e[4] = __expf(v1.x - mx); e[5] = __expf(v1.y - mx);
    e[6] = __expf(v1.z - mx); e[7] = __expf(v1.w - mx);
    float s = e[0]+e[1]+e[2]+e[3]+e[4]+e[5]+e[6]+e[7];
#pragma unroll
    for (int off = 16; off; off >>= 1) s += __shfl_xor_sync(0xffffffffu, s, off);
    if ((t & 31) == 0) shs[t >> 5] = s;
    __syncthreads();
    s = 0.f;
#pragma unroll
    for (int i = 0; i < 8; i++) s += shs[i];
    float inv = 1.f / s;
#pragma unroll
    for (int i = 0; i < 8; i++) e[i] *= inv;
    ((float4*)p)[t]       = make_float4(e[0], e[1], e[2], e[3]);
    ((float4*)p)[t + 256] = make_float4(e[4], e[5], e[6], e[7]);

    __half2* ph = (__half2*)(o + (size_t)blockIdx.x * NS);
    ph[2*t]         = __halves2half2(__float2half(e[0]), __float2half(e[1]));
    ph[2*t+1]       = __halves2half2(__float2half(e[2]), __float2half(e[3]));
    ph[512 + 2*t]   = __halves2half2(__float2half(e[4]), __float2half(e[5]));
    ph[512 + 2*t+1] = __halves2half2(__float2half(e[6]), __float2half(e[7]));
}

// ---------------- weight transpose + split: W[K,N] fp32 -> WT[N,K] fp16 hi/lo ----------------
__global__ void __launch_bounds__(256) wt_conv(const float* __restrict__ W,
                                               __half* __restrict__ Th,
                                               __half* __restrict__ Tl)
{
    __shared__ float tile[64][65];
    int k0 = blockIdx.y * 64, n0 = blockIdx.x * 64;
#pragma unroll
    for (int u = threadIdx.x; u < 4096; u += 256) {
        int r = u >> 6, c = u & 63;
        tile[r][c] = W[(size_t)(k0 + r) * ND + n0 + c];
    }
    __syncthreads();
#pragma unroll
    for (int u = threadIdx.x; u < 4096; u += 256) {
        int r = u >> 6, c = u & 63;
        float v = tile[c][r];
        __half h = __float2half(v);
        Th[(size_t)(n0 + r) * ND + k0 + c] = h;
        Tl[(size_t)(n0 + r) * ND + k0 + c] = __float2half(v - __half2float(h));
    }
}

// ---------------- fp16 transpose (k -> kT per batch) ----------------
__global__ void __launch_bounds__(256) kt_kernel(const __half* __restrict__ ih,
                                                 __half* __restrict__ oh)
{
    __shared__ __half th[64][65];
    int b = blockIdx.z;
    int d0 = blockIdx.x * 64, s0 = blockIdx.y * 64;
    const size_t ib = (size_t)b * NS * ND;
    const size_t ob = (size_t)b * ND * NS;
#pragma unroll
    for (int u = threadIdx.x; u < 4096; u += 256) {
        int r = u >> 6, c = u & 63;
        th[r][c] = ih[ib + (size_t)(s0 + r) * ND + d0 + c];
    }
    __syncthreads();
#pragma unroll
    for (int u = threadIdx.x; u < 4096; u += 256) {
        int r = u >> 6, c = u & 63;
        oh[ob + (size_t)(d0 + r) * NS + s0 + c] = th[c][r];
    }
}

// ---------------- driver ----------------
extern "C" void kernel_launch(void* const* d_in, const int* in_sizes, int n_in,
                              void* d_out, int out_size)
{
    const float* x    = (const float*)d_in[0];
    const int*   mask = (const int*)  d_in[1];
    const float* ln1g = (const float*)d_in[2];
    const float* ln1b = (const float*)d_in[3];
    const float* Wq   = (const float*)d_in[4];
    const float* bq   = (const float*)d_in[5];
    const float* Wk   = (const float*)d_in[6];
    const float* bk   = (const float*)d_in[7];
    const float* Wo   = (const float*)d_in[8];
    const float* bo   = (const float*)d_in[9];
    const float* ln2g = (const float*)d_in[10];
    const float* ln2b = (const float*)d_in[11];
    const float* W1   = (const float*)d_in[12];
    const float* b1   = (const float*)d_in[13];
    const float* W2   = (const float*)d_in[14];
    const float* b2   = (const float*)d_in[15];

    float* out  = (float*)d_out;
    float* wout = out + (size_t)NROWS * ND;

    __half *xn, *q, *k, *kT, *w, *at, *xn2, *h, *wt;
    float* x2;
    cudaGetSymbolAddress((void**)&xn,  g_xn);
    cudaGetSymbolAddress((void**)&q,   g_q);
    cudaGetSymbolAddress((void**)&k,   g_k);
    cudaGetSymbolAddress((void**)&kT,  g_kT);
    cudaGetSymbolAddress((void**)&w,   g_w);
    cudaGetSymbolAddress((void**)&at,  g_at);
    cudaGetSymbolAddress((void**)&xn2, g_xn2);
    cudaGetSymbolAddress((void**)&h,   g_h);
    cudaGetSymbolAddress((void**)&x2,  g_x2);
    cudaGetSymbolAddress((void**)&wt,  g_wt);

    __half *wq_h = wt + 0*2*WSZ, *wq_l = wt + 0*2*WSZ + WSZ;
    __half *wk_h = wt + 1*2*WSZ, *wk_l = wt + 1*2*WSZ + WSZ;
    __half *wo_h = wt + 2*2*WSZ, *wo_l = wt + 2*2*WSZ + WSZ;
    __half *w1_h = wt + 3*2*WSZ, *w1_l = wt + 3*2*WSZ + WSZ;
    __half *w2_h = wt + 4*2*WSZ, *w2_l = wt + 4*2*WSZ + WSZ;

    const int SM2 = NSTG * 24576;   // 2-pass stages
    const int SM1 = NSTG * 16384;   // 1-pass stages

    cudaFuncSetAttribute(gemm_tc<true,false,false,false,true,1>,
                         cudaFuncAttributeMaxDynamicSharedMemorySize, SM2);
    cudaFuncSetAttribute(gemm_tc<false,false,true,false,false,0>,
                         cudaFuncAttributeMaxDynamicSharedMemorySize, SM1);
    cudaFuncSetAttribute(gemm_tc<false,false,false,false,false,1>,
                         cudaFuncAttributeMaxDynamicSharedMemorySize, SM1);
    cudaFuncSetAttribute(gemm_tc<true,false,false,true,false,0>,
                         cudaFuncAttributeMaxDynamicSharedMemorySize, SM1);
    cudaFuncSetAttribute(gemm_tc<true,true,false,false,false,1>,
                         cudaFuncAttributeMaxDynamicSharedMemorySize, SM1);

    dim3 gW(16, 16);
    wt_conv<<<gW, 256>>>(Wq, wq_h, wq_l);
    wt_conv<<<gW, 256>>>(Wk, wk_h, wk_l);
    wt_conv<<<gW, 256>>>(Wo, wo_h, wo_l);
    wt_conv<<<gW, 256>>>(W1, w1_h, w1_l);
    wt_conv<<<gW, 256>>>(W2, w2_h, w2_l);

    // 1) xn = LN1(x)
    ln_f16<<<NROWS, 256>>>(x, ln1g, ln1b, xn);

    dim3 gP(ND / 128, NROWS / 128, 1);
    // 2) q = xn@Wq+bq ; k = xn@Wk+bk  (2-pass: protects attention precision; v == k)
    gemm_tc<true,false,false,false,true,1><<<gP, 256, SM2>>>(
        xn, wq_h, wq_l, NROWS, ND, ND, 0, 0, 0,
        nullptr, q, bq, nullptr, nullptr, 1.f);
    gemm_tc<true,false,false,false,true,1><<<gP, 256, SM2>>>(
        xn, wk_h, wk_l, NROWS, ND, ND, 0, 0, 0,
        nullptr, k, bk, nullptr, nullptr, 1.f);

    // 3) kT for attn@v
    kt_kernel<<<dim3(ND / 64, NS / 64, NB), 256>>>(k, kT);

    // 4) scores = (q @ k^T)/32, masked -> wout (fp32), 1-pass
    dim3 gS(NS / 128, NS / 128, NB);
    gemm_tc<false,false,true,false,false,0><<<gS, 256, SM1>>>(
        q, k, nullptr, NS, NS, ND,
        (long long)NS * ND, (long long)NS * ND, (long long)NS * NS,
        wout, nullptr, nullptr, nullptr, mask, 0.03125f);

    // 5) softmax in place + fp16 w
    softmax_f16<<<NROWS, 256>>>(wout, w);

    // 6) attn = w @ v  (v == k), 1-pass
    dim3 gA(ND / 128, NS / 128, NB);
    gemm_tc<false,false,false,false,false,1><<<gA, 256, SM1>>>(
        w, kT, nullptr, NS, ND, NS,
        (long long)NS * NS, (long long)ND * NS, (long long)NS * ND,
        nullptr, at, nullptr, nullptr, nullptr, 1.f);

    // 7) x2 = x + attn @ Wo + bo   (1-pass weight)
    gemm_tc<true,false,false,true,false,0><<<gP, 256, SM1>>>(
        at, wo_h, nullptr, NROWS, ND, ND, 0, 0, 0,
        x2, nullptr, bo, x, nullptr, 1.f);

    // 8) xn2 = LN2(x2)
    ln_f16<<<NROWS, 256>>>(x2, ln2g, ln2b, xn2);

    // 9) h = relu(xn2 @ W1 + b1)   (1-pass weight)
    gemm_tc<true,true,false,false,false,1><<<gP, 256, SM1>>>(
        xn2, w1_h, nullptr, NROWS, ND, ND, 0, 0, 0,
        nullptr, h, b1, nullptr, nullptr, 1.f);

    // 10) out = x2 + h @ W2 + b2   (1-pass weight)
    gemm_tc<true,false,false,true,false,0><<<gP, 256, SM1>>>(
        h, w2_h, nullptr, NROWS, ND, ND, 0, 0, 0,
        out, nullptr, b2, x2, nullptr, 1.f);
}

// round 9
// speedup vs baseline: 2.2929x; 1.1217x over previous
#include <cuda_runtime.h>
#include <cuda_fp16.h>
#include <stdint.h>

#define NB 8
#define NS 2048
#define ND 1024
#define NROWS (NB * NS)          // 16384
#define WSZ ((size_t)ND * ND)

// ---------------- scratch (no cudaMalloc allowed) ----------------
__device__ __half g_xn  [(size_t)NROWS * ND];
__device__ __half g_q   [(size_t)NROWS * ND];
__device__ __half g_k   [(size_t)NROWS * ND];
__device__ __half g_kT  [(size_t)NROWS * ND];
__device__ __half g_w   [(size_t)NB * NS * NS];
__device__ __half g_at  [(size_t)NROWS * ND];
__device__ float  g_x2  [(size_t)NROWS * ND];
__device__ __half g_xn2 [(size_t)NROWS * ND];
__device__ __half g_h   [(size_t)NROWS * ND];
__device__ __half g_wt  [5 * WSZ];   // 5 transposed fp16 weights

// ---------------- helpers ----------------
__device__ __forceinline__ uint32_t smem_u32(const void* p) {
    uint32_t a;
    asm("{ .reg .u64 t; cvta.to.shared.u64 t, %1; cvt.u32.u64 %0, t; }" : "=r"(a) : "l"(p));
    return a;
}
__device__ __forceinline__ void cp16(uint32_t dst, const void* src) {
    asm volatile("cp.async.cg.shared.global [%0], [%1], 16;" :: "r"(dst), "l"(src));
}
__device__ __forceinline__ void ldmA(uint32_t* a, uint32_t addr) {
    asm volatile("ldmatrix.sync.aligned.m8n8.x4.shared.b16 {%0,%1,%2,%3}, [%4];"
                 : "=r"(a[0]), "=r"(a[1]), "=r"(a[2]), "=r"(a[3]) : "r"(addr));
}
__device__ __forceinline__ void ldmB(uint32_t* b, uint32_t addr) {
    asm volatile("ldmatrix.sync.aligned.m8n8.x2.shared.b16 {%0,%1}, [%2];"
                 : "=r"(b[0]), "=r"(b[1]) : "r"(addr));
}
__device__ __forceinline__ void mma16816(float* c, const uint32_t* a, const uint32_t* b) {
    asm volatile("mma.sync.aligned.m16n8k16.row.col.f32.f16.f16.f32 "
                 "{%0,%1,%2,%3}, {%4,%5,%6,%7}, {%8,%9}, {%0,%1,%2,%3};"
                 : "+f"(c[0]), "+f"(c[1]), "+f"(c[2]), "+f"(c[3])
                 : "r"(a[0]), "r"(a[1]), "r"(a[2]), "r"(a[3]), "r"(b[0]), "r"(b[1]));
}

#define NSTG 3
#define STAGE 16384u
#define SMEMSZ (NSTG * STAGE)
// tile offset inside an 8K operand block: 8x8 fp16 tiles, id = kt8*16 + rt8
__device__ __forceinline__ uint32_t toff(int rt8, int kt8) {
    return (uint32_t)((kt8 * 16 + rt8) * 128);
}

// ---------------- warp-MMA fp16 GEMM: 128x128 CTA tile, kchunk 32, 1 pass ----------------
// D = alpha * A[M,K](fp16) * B[N,K]^T  (+bias) (mask==0 -> -1e9) (+resid) (relu)
// OUT: 0 = fp32, 1 = fp16
template <bool BIAS, bool RELU, bool MASK, bool RESID, int OUT>
__global__ void __launch_bounds__(256, 2) gemm_tc(
    const __half* __restrict__ A,
    const __half* __restrict__ B,
    int M, int N, int K,
    long long sA, long long sB, long long sC,
    float* __restrict__ Cf,
    __half* __restrict__ Ch,
    const float* __restrict__ bias,
    const float* __restrict__ resid,
    const int* __restrict__ mask,
    float alpha)
{
    extern __shared__ char smem[];
    const int tid  = threadIdx.x;
    const int lane = tid & 31, wid = tid >> 5;
    const int wm = wid & 1, wn = wid >> 1;          // 2 x 4 warp grid, warp tile 64x32
    const int bz = blockIdx.z;
    A += (size_t)bz * sA; B += (size_t)bz * sB;
    const size_t coff = (size_t)bz * sC;
    if (OUT == 0) Cf += coff; else Ch += coff;
    const int m0 = blockIdx.y * 128, n0 = blockIdx.x * 128;

    const uint32_t sb = smem_u32(smem);

    float acc[4][4][4];
#pragma unroll
    for (int i = 0; i < 4; i++)
#pragma unroll
        for (int j = 0; j < 4; j++)
#pragma unroll
            for (int q = 0; q < 4; q++) acc[i][j][q] = 0.f;

    const int nk = K >> 5;

    // staging map: idx -> row = idx>>2, kt8 = idx&3 (8x8 tiles contiguous 128B)
    const int r_lo = tid >> 2, kt = tid & 3;
    const uint32_t d_lo = (uint32_t)((kt * 16 + (r_lo >> 3)) * 128 + (r_lo & 7) * 16);
    const int r_hi = r_lo + 64;
    const uint32_t d_hi = (uint32_t)((kt * 16 + (r_hi >> 3)) * 128 + (r_hi & 7) * 16);

    auto issue = [&](int i) {
        const uint32_t s = sb + (uint32_t)(i % NSTG) * STAGE;
        const int k0 = i << 5;
        const size_t ga_lo = (size_t)(m0 + r_lo) * K + k0 + kt * 8;
        const size_t ga_hi = (size_t)(m0 + r_hi) * K + k0 + kt * 8;
        const size_t gb_lo = (size_t)(n0 + r_lo) * K + k0 + kt * 8;
        const size_t gb_hi = (size_t)(n0 + r_hi) * K + k0 + kt * 8;
        cp16(s + d_lo,        A + ga_lo);
        cp16(s + d_hi,        A + ga_hi);
        cp16(s + 8192 + d_lo, B + gb_lo);
        cp16(s + 8192 + d_hi, B + gb_hi);
        asm volatile("cp.async.commit_group;");
    };

    issue(0);
    issue(1);
    const int mrow16 = (lane & 7) * 16;
    const int bmi = (lane >> 3) & 1;                 // B x2 k-subtile select
    const int dm = (lane >> 3) & 1, dk = lane >> 4;  // A x4 decode

    for (int i = 0; i < nk; i++) {
        if (i == nk - 1) asm volatile("cp.async.wait_group 0;");
        else             asm volatile("cp.async.wait_group 1;");
        __syncthreads();
        if (i + 2 < nk) issue(i + 2);

        const uint32_t st  = sb + (uint32_t)(i % NSTG) * STAGE;
        const uint32_t sAa = st;
        const uint32_t sBb = st + 8192;

#pragma unroll
        for (int ks = 0; ks < 2; ks++) {
            uint32_t a[4][4];
#pragma unroll
            for (int mt = 0; mt < 4; mt++) {
                const int mt8 = wm * 8 + mt * 2 + dm;
                ldmA(a[mt], sAa + toff(mt8, ks * 2 + dk) + mrow16);
            }
            uint32_t bh[4][2];
#pragma unroll
            for (int nt = 0; nt < 4; nt++)
                ldmB(bh[nt], sBb + toff(wn * 4 + nt, ks * 2 + bmi) + mrow16);
            // 16 independent accumulators back-to-back
#pragma unroll
            for (int mt = 0; mt < 4; mt++)
#pragma unroll
                for (int nt = 0; nt < 4; nt++)
                    mma16816(acc[mt][nt], a[mt], bh[nt]);
        }
    }

    // ---------------- epilogue ----------------
    const int cq = (lane & 3) * 2, rq = lane >> 2;
#pragma unroll
    for (int nt = 0; nt < 4; nt++) {
        const int c = n0 + wn * 32 + nt * 8 + cq;
        float bv0 = 0.f, bv1 = 0.f;
        if (BIAS) { bv0 = bias[c]; bv1 = bias[c + 1]; }
        int mk0 = 1, mk1 = 1;
        if (MASK) {
            const int* mp = mask + (size_t)bz * N;
            mk0 = mp[c]; mk1 = mp[c + 1];
        }
#pragma unroll
        for (int mt = 0; mt < 4; mt++) {
            const int r0 = m0 + wm * 64 + mt * 16 + rq;
#pragma unroll
            for (int h = 0; h < 2; h++) {
                const int row = r0 + h * 8;
                float v0 = acc[mt][nt][h * 2 + 0] * alpha + bv0;
                float v1 = acc[mt][nt][h * 2 + 1] * alpha + bv1;
                if (MASK) { if (mk0 == 0) v0 = -1e9f; if (mk1 == 0) v1 = -1e9f; }
                if (RESID) {
                    float2 rv = *(const float2*)(resid + (size_t)row * N + c);
                    v0 += rv.x; v1 += rv.y;
                }
                if (RELU) { v0 = fmaxf(v0, 0.f); v1 = fmaxf(v1, 0.f); }
                if (OUT == 0) {
                    *(float2*)(Cf + (size_t)row * N + c) = make_float2(v0, v1);
                } else {
                    *(__half2*)(Ch + (size_t)row * N + c) =
                        __halves2half2(__float2half(v0), __float2half(v1));
                }
            }
        }
    }
}

// ---------------- LayerNorm -> fp16 ----------------
__global__ void __launch_bounds__(256) ln_f16(const float* __restrict__ x,
                                              const float* __restrict__ g,
                                              const float* __restrict__ b,
                                              __half* __restrict__ o)
{
    size_t row = blockIdx.x;
    int t = threadIdx.x;
    float4 xv = ((const float4*)(x + row * ND))[t];
    float s  = xv.x + xv.y + xv.z + xv.w;
    float ss = xv.x*xv.x + xv.y*xv.y + xv.z*xv.z + xv.w*xv.w;
#pragma unroll
    for (int off = 16; off; off >>= 1) {
        s  += __shfl_xor_sync(0xffffffffu, s,  off);
        ss += __shfl_xor_sync(0xffffffffu, ss, off);
    }
    __shared__ float sh_s[8], sh_ss[8];
    if ((t & 31) == 0) { sh_s[t >> 5] = s; sh_ss[t >> 5] = ss; }
    __syncthreads();
    float ts = 0.f, tss = 0.f;
#pragma unroll
    for (int i = 0; i < 8; i++) { ts += sh_s[i]; tss += sh_ss[i]; }
    float mean = ts * (1.f / ND);
    float var  = tss * (1.f / ND) - mean * mean;
    float rstd = rsqrtf(var + 1e-5f);
    float4 gv = ((const float4*)g)[t];
    float4 bv = ((const float4*)b)[t];
    float o0 = (xv.x - mean) * rstd * gv.x + bv.x;
    float o1 = (xv.y - mean) * rstd * gv.y + bv.y;
    float o2 = (xv.z - mean) * rstd * gv.z + bv.z;
    float o3 = (xv.w - mean) * rstd * gv.w + bv.w;
    __half2* ph = (__half2*)(o + row * ND);
    ph[2*t]   = __halves2half2(__float2half(o0), __float2half(o1));
    ph[2*t+1] = __halves2half2(__float2half(o2), __float2half(o3));
}

// ---------------- softmax (fp32 in-place) + fp16 emission ----------------
__global__ void __launch_bounds__(256) softmax_f16(float* __restrict__ w,
                                                   __half* __restrict__ o)
{
    float* p = w + (size_t)blockIdx.x * NS;
    int t = threadIdx.x;
    float4 v0 = ((const float4*)p)[t];
    float4 v1 = ((const float4*)p)[t + 256];
    float mx = fmaxf(fmaxf(fmaxf(v0.x, v0.y), fmaxf(v0.z, v0.w)),
                     fmaxf(fmaxf(v1.x, v1.y), fmaxf(v1.z, v1.w)));
#pragma unroll
    for (int off = 16; off; off >>= 1) mx = fmaxf(mx, __shfl_xor_sync(0xffffffffu, mx, off));
    __shared__ float shm[8], shs[8];
    if ((t & 31) == 0) shm[t >> 5] = mx;
    __syncthreads();
    mx = shm[0];
#pragma unroll
    for (int i = 1; i < 8; i++) mx = fmaxf(mx, shm[i]);
    float e[8];
    e[0] = __expf(v0.x - mx); e[1] = __expf(v0.y - mx);
    e[2] = __expf(v0.z - mx); e[3] = __expf(v0.w - mx);
    e[4] = __expf(v1.x - mx); e[5] = __expf(v1.y - mx);
    e[6] = __expf(v1.z - mx); e[7] = __expf(v1.w - mx);
    float s = e[0]+e[1]+e[2]+e[3]+e[4]+e[5]+e[6]+e[7];
#pragma unroll
    for (int off = 16; off; off >>= 1) s += __shfl_xor_sync(0xffffffffu, s, off);
    if ((t & 31) == 0) shs[t >> 5] = s;
    __syncthreads();
    s = 0.f;
#pragma unroll
    for (int i = 0; i < 8; i++) s += shs[i];
    float inv = 1.f / s;
#pragma unroll
    for (int i = 0; i < 8; i++) e[i] *= inv;
    ((float4*)p)[t]       = make_float4(e[0], e[1], e[2], e[3]);
    ((float4*)p)[t + 256] = make_float4(e[4], e[5], e[6], e[7]);

    __half2* ph = (__half2*)(o + (size_t)blockIdx.x * NS);
    ph[2*t]         = __halves2half2(__float2half(e[0]), __float2half(e[1]));
    ph[2*t+1]       = __halves2half2(__float2half(e[2]), __float2half(e[3]));
    ph[512 + 2*t]   = __halves2half2(__float2half(e[4]), __float2half(e[5]));
    ph[512 + 2*t+1] = __halves2half2(__float2half(e[6]), __float2half(e[7]));
}

// ---------------- weight transpose: W[K,N] fp32 -> WT[N,K] fp16 ----------------
__global__ void __launch_bounds__(256) wt_conv(const float* __restrict__ W,
                                               __half* __restrict__ Th)
{
    __shared__ float tile[64][65];
    int k0 = blockIdx.y * 64, n0 = blockIdx.x * 64;
#pragma unroll
    for (int u = threadIdx.x; u < 4096; u += 256) {
        int r = u >> 6, c = u & 63;
        tile[r][c] = W[(size_t)(k0 + r) * ND + n0 + c];
    }
    __syncthreads();
#pragma unroll
    for (int u = threadIdx.x; u < 4096; u += 256) {
        int r = u >> 6, c = u & 63;
        Th[(size_t)(n0 + r) * ND + k0 + c] = __float2half(tile[c][r]);
    }
}

// ---------------- fp16 transpose (k -> kT per batch) ----------------
__global__ void __launch_bounds__(256) kt_kernel(const __half* __restrict__ ih,
                                                 __half* __restrict__ oh)
{
    __shared__ __half th[64][65];
    int b = blockIdx.z;
    int d0 = blockIdx.x * 64, s0 = blockIdx.y * 64;
    const size_t ib = (size_t)b * NS * ND;
    const size_t ob = (size_t)b * ND * NS;
#pragma unroll
    for (int u = threadIdx.x; u < 4096; u += 256) {
        int r = u >> 6, c = u & 63;
        th[r][c] = ih[ib + (size_t)(s0 + r) * ND + d0 + c];
    }
    __syncthreads();
#pragma unroll
    for (int u = threadIdx.x; u < 4096; u += 256) {
        int r = u >> 6, c = u & 63;
        oh[ob + (size_t)(d0 + r) * NS + s0 + c] = th[c][r];
    }
}

// ---------------- driver ----------------
extern "C" void kernel_launch(void* const* d_in, const int* in_sizes, int n_in,
                              void* d_out, int out_size)
{
    const float* x    = (const float*)d_in[0];
    const int*   mask = (const int*)  d_in[1];
    const float* ln1g = (const float*)d_in[2];
    const float* ln1b = (const float*)d_in[3];
    const float* Wq   = (const float*)d_in[4];
    const float* bq   = (const float*)d_in[5];
    const float* Wk   = (const float*)d_in[6];
    const float* bk   = (const float*)d_in[7];
    const float* Wo   = (const float*)d_in[8];
    const float* bo   = (const float*)d_in[9];
    const float* ln2g = (const float*)d_in[10];
    const float* ln2b = (const float*)d_in[11];
    const float* W1   = (const float*)d_in[12];
    const float* b1   = (const float*)d_in[13];
    const float* W2   = (const float*)d_in[14];
    const float* b2   = (const float*)d_in[15];

    float* out  = (float*)d_out;
    float* wout = out + (size_t)NROWS * ND;

    __half *xn, *q, *k, *kT, *w, *at, *xn2, *h, *wt;
    float* x2;
    cudaGetSymbolAddress((void**)&xn,  g_xn);
    cudaGetSymbolAddress((void**)&q,   g_q);
    cudaGetSymbolAddress((void**)&k,   g_k);
    cudaGetSymbolAddress((void**)&kT,  g_kT);
    cudaGetSymbolAddress((void**)&w,   g_w);
    cudaGetSymbolAddress((void**)&at,  g_at);
    cudaGetSymbolAddress((void**)&xn2, g_xn2);
    cudaGetSymbolAddress((void**)&h,   g_h);
    cudaGetSymbolAddress((void**)&x2,  g_x2);
    cudaGetSymbolAddress((void**)&wt,  g_wt);

    __half *wq_t = wt + 0*WSZ;
    __half *wk_t = wt + 1*WSZ;
    __half *wo_t = wt + 2*WSZ;
    __half *w1_t = wt + 3*WSZ;
    __half *w2_t = wt + 4*WSZ;

    cudaFuncSetAttribute(gemm_tc<true,false,false,false,1>,
                         cudaFuncAttributeMaxDynamicSharedMemorySize, SMEMSZ);
    cudaFuncSetAttribute(gemm_tc<false,false,true,false,0>,
                         cudaFuncAttributeMaxDynamicSharedMemorySize, SMEMSZ);
    cudaFuncSetAttribute(gemm_tc<false,false,false,false,1>,
                         cudaFuncAttributeMaxDynamicSharedMemorySize, SMEMSZ);
    cudaFuncSetAttribute(gemm_tc<true,false,false,true,0>,
                         cudaFuncAttributeMaxDynamicSharedMemorySize, SMEMSZ);
    cudaFuncSetAttribute(gemm_tc<true,true,false,false,1>,
                         cudaFuncAttributeMaxDynamicSharedMemorySize, SMEMSZ);

    dim3 gW(16, 16);
    wt_conv<<<gW, 256>>>(Wq, wq_t);
    wt_conv<<<gW, 256>>>(Wk, wk_t);
    wt_conv<<<gW, 256>>>(Wo, wo_t);
    wt_conv<<<gW, 256>>>(W1, w1_t);
    wt_conv<<<gW, 256>>>(W2, w2_t);

    // 1) xn = LN1(x)
    ln_f16<<<NROWS, 256>>>(x, ln1g, ln1b, xn);

    dim3 gP(ND / 128, NROWS / 128, 1);
    // 2) q = xn@Wq+bq ; k = xn@Wk+bk  (1-pass; v == k, faithful reference bug)
    gemm_tc<true,false,false,false,1><<<gP, 256, SMEMSZ>>>(
        xn, wq_t, NROWS, ND, ND, 0, 0, 0,
        nullptr, q, bq, nullptr, nullptr, 1.f);
    gemm_tc<true,false,false,false,1><<<gP, 256, SMEMSZ>>>(
        xn, wk_t, NROWS, ND, ND, 0, 0, 0,
        nullptr, k, bk, nullptr, nullptr, 1.f);

    // 3) kT for attn@v
    kt_kernel<<<dim3(ND / 64, NS / 64, NB), 256>>>(k, kT);

    // 4) scores = (q @ k^T)/32, masked -> wout (fp32)
    dim3 gS(NS / 128, NS / 128, NB);
    gemm_tc<false,false,true,false,0><<<gS, 256, SMEMSZ>>>(
        q, k, NS, NS, ND,
        (long long)NS * ND, (long long)NS * ND, (long long)NS * NS,
        wout, nullptr, nullptr, nullptr, mask, 0.03125f);

    // 5) softmax in place + fp16 w
    softmax_f16<<<NROWS, 256>>>(wout, w);

    // 6) attn = w @ v  (v == k)
    dim3 gA(ND / 128, NS / 128, NB);
    gemm_tc<false,false,false,false,1><<<gA, 256, SMEMSZ>>>(
        w, kT, NS, ND, NS,
        (long long)NS * NS, (long long)ND * NS, (long long)NS * ND,
        nullptr, at, nullptr, nullptr, nullptr, 1.f);

    // 7) x2 = x + attn @ Wo + bo
    gemm_tc<true,false,false,true,0><<<gP, 256, SMEMSZ>>>(
        at, wo_t, NROWS, ND, ND, 0, 0, 0,
        x2, nullptr, bo, x, nullptr, 1.f);

    // 8) xn2 = LN2(x2)
    ln_f16<<<NROWS, 256>>>(x2, ln2g, ln2b, xn2);

    // 9) h = relu(xn2 @ W1 + b1)
    gemm_tc<true,true,false,false,1><<<gP, 256, SMEMSZ>>>(
        xn2, w1_t, NROWS, ND, ND, 0, 0, 0,
        nullptr, h, b1, nullptr, nullptr, 1.f);

    // 10) out = x2 + h @ W2 + b2
    gemm_tc<true,false,false,true,0><<<gP, 256, SMEMSZ>>>(
        h, w2_t, NROWS, ND, ND, 0, 0, 0,
        out, nullptr, b2, x2, nullptr, 1.f);
}

// round 10
// speedup vs baseline: 2.3034x; 1.0045x over previous
#include <cuda_runtime.h>
#include <cuda_fp16.h>
#include <stdint.h>

#define NB 8
#define NS 2048
#define ND 1024
#define NROWS (NB * NS)          // 16384
#define WSZ ((size_t)ND * ND)

// ---------------- scratch (no cudaMalloc allowed) ----------------
__device__ __half g_xn  [(size_t)NROWS * ND];
__device__ __half g_q   [(size_t)NROWS * ND];
__device__ __half g_k   [(size_t)NROWS * ND];
__device__ __half g_kT  [(size_t)NROWS * ND];
__device__ __half g_w   [(size_t)NB * NS * NS];
__device__ __half g_at  [(size_t)NROWS * ND];
__device__ float  g_x2  [(size_t)NROWS * ND];
__device__ __half g_xn2 [(size_t)NROWS * ND];
__device__ __half g_h   [(size_t)NROWS * ND];
__device__ __half g_wt  [5 * WSZ];   // 5 transposed fp16 weights

// ---------------- helpers ----------------
__device__ __forceinline__ uint32_t smem_u32(const void* p) {
    uint32_t a;
    asm("{ .reg .u64 t; cvta.to.shared.u64 t, %1; cvt.u32.u64 %0, t; }" : "=r"(a) : "l"(p));
    return a;
}
__device__ __forceinline__ void cp16(uint32_t dst, const void* src) {
    asm volatile("cp.async.cg.shared.global [%0], [%1], 16;" :: "r"(dst), "l"(src));
}
__device__ __forceinline__ void ldmA(uint32_t* a, uint32_t addr) {
    asm volatile("ldmatrix.sync.aligned.m8n8.x4.shared.b16 {%0,%1,%2,%3}, [%4];"
                 : "=r"(a[0]), "=r"(a[1]), "=r"(a[2]), "=r"(a[3]) : "r"(addr));
}
__device__ __forceinline__ void ldmB(uint32_t* b, uint32_t addr) {
    asm volatile("ldmatrix.sync.aligned.m8n8.x2.shared.b16 {%0,%1}, [%2];"
                 : "=r"(b[0]), "=r"(b[1]) : "r"(addr));
}
__device__ __forceinline__ void mma16816(float* c, const uint32_t* a, const uint32_t* b) {
    asm volatile("mma.sync.aligned.m16n8k16.row.col.f32.f16.f16.f32 "
                 "{%0,%1,%2,%3}, {%4,%5,%6,%7}, {%8,%9}, {%0,%1,%2,%3};"
                 : "+f"(c[0]), "+f"(c[1]), "+f"(c[2]), "+f"(c[3])
                 : "r"(a[0]), "r"(a[1]), "r"(a[2]), "r"(a[3]), "r"(b[0]), "r"(b[1]));
}

#define NSTG 3
#define STAGE 32768u               // A 16K | B 16K  (kchunk = 64)
#define SMEMSZ (NSTG * STAGE)      // 96 KB -> 2 CTAs/SM
// tile offset inside a 16K operand block: 8x8 fp16 tiles, id = kt8*16 + rt8
__device__ __forceinline__ uint32_t toff(int rt8, int kt8) {
    return (uint32_t)((kt8 * 16 + rt8) * 128);
}

// ---------------- warp-MMA fp16 GEMM: 128x128 CTA tile, kchunk 64, 1 pass ----------------
// D = alpha * A[M,K](fp16) * B[N,K]^T  (+bias) (mask==0 -> -1e9) (+resid) (relu)
// OUT: 0 = fp32, 1 = fp16
template <bool BIAS, bool RELU, bool MASK, bool RESID, int OUT>
__global__ void __launch_bounds__(256, 2) gemm_tc(
    const __half* __restrict__ A,
    const __half* __restrict__ B,
    int M, int N, int K,
    long long sA, long long sB, long long sC,
    float* __restrict__ Cf,
    __half* __restrict__ Ch,
    const float* __restrict__ bias,
    const float* __restrict__ resid,
    const int* __restrict__ mask,
    float alpha)
{
    extern __shared__ char smem[];
    const int tid  = threadIdx.x;
    const int lane = tid & 31, wid = tid >> 5;
    const int wm = wid & 1, wn = wid >> 1;          // 2 x 4 warp grid, warp tile 64x32
    const int bz = blockIdx.z;
    A += (size_t)bz * sA; B += (size_t)bz * sB;
    const size_t coff = (size_t)bz * sC;
    if (OUT == 0) Cf += coff; else Ch += coff;
    const int m0 = blockIdx.y * 128, n0 = blockIdx.x * 128;

    const uint32_t sb = smem_u32(smem);

    float acc[4][4][4];
#pragma unroll
    for (int i = 0; i < 4; i++)
#pragma unroll
        for (int j = 0; j < 4; j++)
#pragma unroll
            for (int q = 0; q < 4; q++) acc[i][j][q] = 0.f;

    const int nk = K >> 6;                           // 64-wide chunks

    // staging map: idx = tid + h*256 -> row = idx>>3, kt8 = idx&7 (64 cols = 8 k-tiles)
    const int s_row = tid >> 3, s_kt = tid & 7;
    uint32_t doff[4];
    int      srow[4];
#pragma unroll
    for (int h = 0; h < 4; h++) {
        const int r = s_row + h * 32;                // 4 x 32 rows = 128
        srow[h] = r;
        doff[h] = (uint32_t)((s_kt * 16 + (r >> 3)) * 128 + (r & 7) * 16);
    }

    auto issue = [&](int i) {
        const uint32_t s = sb + (uint32_t)(i % NSTG) * STAGE;
        const int k0 = i << 6;
#pragma unroll
        for (int h = 0; h < 4; h++) {
            const size_t ga = (size_t)(m0 + srow[h]) * K + k0 + s_kt * 8;
            const size_t gb = (size_t)(n0 + srow[h]) * K + k0 + s_kt * 8;
            cp16(s + doff[h],         A + ga);
            cp16(s + 16384 + doff[h], B + gb);
        }
        asm volatile("cp.async.commit_group;");
    };

    issue(0);
    issue(1);
    const int mrow16 = (lane & 7) * 16;
    const int bmi = (lane >> 3) & 1;                 // B x2 k-subtile select
    const int dm = (lane >> 3) & 1, dk = lane >> 4;  // A x4 decode

    for (int i = 0; i < nk; i++) {
        if (i == nk - 1) asm volatile("cp.async.wait_group 0;");
        else             asm volatile("cp.async.wait_group 1;");
        __syncthreads();
        if (i + 2 < nk) issue(i + 2);

        const uint32_t st  = sb + (uint32_t)(i % NSTG) * STAGE;
        const uint32_t sAa = st;
        const uint32_t sBb = st + 16384;

#pragma unroll
        for (int ks = 0; ks < 4; ks++) {             // 4 k16 subtiles per 64-chunk
            uint32_t a[4][4];
#pragma unroll
            for (int mt = 0; mt < 4; mt++) {
                const int mt8 = wm * 8 + mt * 2 + dm;
                ldmA(a[mt], sAa + toff(mt8, ks * 2 + dk) + mrow16);
            }
            uint32_t bh[4][2];
#pragma unroll
            for (int nt = 0; nt < 4; nt++)
                ldmB(bh[nt], sBb + toff(wn * 4 + nt, ks * 2 + bmi) + mrow16);
            // 16 independent accumulators back-to-back
#pragma unroll
            for (int mt = 0; mt < 4; mt++)
#pragma unroll
                for (int nt = 0; nt < 4; nt++)
                    mma16816(acc[mt][nt], a[mt], bh[nt]);
        }
    }

    // ---------------- epilogue ----------------
    const int cq = (lane & 3) * 2, rq = lane >> 2;
#pragma unroll
    for (int nt = 0; nt < 4; nt++) {
        const int c = n0 + wn * 32 + nt * 8 + cq;
        float bv0 = 0.f, bv1 = 0.f;
        if (BIAS) { bv0 = bias[c]; bv1 = bias[c + 1]; }
        int mk0 = 1, mk1 = 1;
        if (MASK) {
            const int* mp = mask + (size_t)bz * N;
            mk0 = mp[c]; mk1 = mp[c + 1];
        }
#pragma unroll
        for (int mt = 0; mt < 4; mt++) {
            const int r0 = m0 + wm * 64 + mt * 16 + rq;
#pragma unroll
            for (int h = 0; h < 2; h++) {
                const int row = r0 + h * 8;
                float v0 = acc[mt][nt][h * 2 + 0] * alpha + bv0;
                float v1 = acc[mt][nt][h * 2 + 1] * alpha + bv1;
                if (MASK) { if (mk0 == 0) v0 = -1e9f; if (mk1 == 0) v1 = -1e9f; }
                if (RESID) {
                    float2 rv = *(const float2*)(resid + (size_t)row * N + c);
                    v0 += rv.x; v1 += rv.y;
                }
                if (RELU) { v0 = fmaxf(v0, 0.f); v1 = fmaxf(v1, 0.f); }
                if (OUT == 0) {
                    *(float2*)(Cf + (size_t)row * N + c) = make_float2(v0, v1);
                } else {
                    *(__half2*)(Ch + (size_t)row * N + c) =
                        __halves2half2(__float2half(v0), __float2half(v1));
                }
            }
        }
    }
}

// ---------------- LayerNorm -> fp16 ----------------
__global__ void __launch_bounds__(256) ln_f16(const float* __restrict__ x,
                                              const float* __restrict__ g,
                                              const float* __restrict__ b,
                                              __half* __restrict__ o)
{
    size_t row = blockIdx.x;
    int t = threadIdx.x;
    float4 xv = ((const float4*)(x + row * ND))[t];
    float s  = xv.x + xv.y + xv.z + xv.w;
    float ss = xv.x*xv.x + xv.y*xv.y + xv.z*xv.z + xv.w*xv.w;
#pragma unroll
    for (int off = 16; off; off >>= 1) {
        s  += __shfl_xor_sync(0xffffffffu, s,  off);
        ss += __shfl_xor_sync(0xffffffffu, ss, off);
    }
    __shared__ float sh_s[8], sh_ss[8];
    if ((t & 31) == 0) { sh_s[t >> 5] = s; sh_ss[t >> 5] = ss; }
    __syncthreads();
    float ts = 0.f, tss = 0.f;
#pragma unroll
    for (int i = 0; i < 8; i++) { ts += sh_s[i]; tss += sh_ss[i]; }
    float mean = ts * (1.f / ND);
    float var  = tss * (1.f / ND) - mean * mean;
    float rstd = rsqrtf(var + 1e-5f);
    float4 gv = ((const float4*)g)[t];
    float4 bv = ((const float4*)b)[t];
    float o0 = (xv.x - mean) * rstd * gv.x + bv.x;
    float o1 = (xv.y - mean) * rstd * gv.y + bv.y;
    float o2 = (xv.z - mean) * rstd * gv.z + bv.z;
    float o3 = (xv.w - mean) * rstd * gv.w + bv.w;
    __half2* ph = (__half2*)(o + row * ND);
    ph[2*t]   = __halves2half2(__float2half(o0), __float2half(o1));
    ph[2*t+1] = __halves2half2(__float2half(o2), __float2half(o3));
}

// ---------------- softmax (fp32 in-place) + fp16 emission ----------------
__global__ void __launch_bounds__(256) softmax_f16(float* __restrict__ w,
                                                   __half* __restrict__ o)
{
    float* p = w + (size_t)blockIdx.x * NS;
    int t = threadIdx.x;
    float4 v0 = ((const float4*)p)[t];
    float4 v1 = ((const float4*)p)[t + 256];
    float mx = fmaxf(fmaxf(fmaxf(v0.x, v0.y), fmaxf(v0.z, v0.w)),
                     fmaxf(fmaxf(v1.x, v1.y), fmaxf(v1.z, v1.w)));
#pragma unroll
    for (int off = 16; off; off >>= 1) mx = fmaxf(mx, __shfl_xor_sync(0xffffffffu, mx, off));
    __shared__ float shm[8], shs[8];
    if ((t & 31) == 0) shm[t >> 5] = mx;
    __syncthreads();
    mx = shm[0];
#pragma unroll
    for (int i = 1; i < 8; i++) mx = fmaxf(mx, shm[i]);
    float e[8];
    e[0] = __expf(v0.x - mx); e[1] = __expf(v0.y - mx);
    e[2] = __expf(v0.z - mx); e[3] = __expf(v0.w - mx);
    e[4] = __expf(v1.x - mx); e[5] = __expf(v1.y - mx);
    e[6] = __expf(v1.z - mx); e[7] = __expf(v1.w - mx);
    float s = e[0]+e[1]+e[2]+e[3]+e[4]+e[5]+e[6]+e[7];
#pragma unroll
    for (int off = 16; off; off >>= 1) s += __shfl_xor_sync(0xffffffffu, s, off);
    if ((t & 31) == 0) shs[t >> 5] = s;
    __syncthreads();
    s = 0.f;
#pragma unroll
    for (int i = 0; i < 8; i++) s += shs[i];
    float inv = 1.f / s;
#pragma unroll
    for (int i = 0; i < 8; i++) e[i] *= inv;
    ((float4*)p)[t]       = make_float4(e[0], e[1], e[2], e[3]);
    ((float4*)p)[t + 256] = make_float4(e[4], e[5], e[6], e[7]);

    __half2* ph = (__half2*)(o + (size_t)blockIdx.x * NS);
    ph[2*t]         = __halves2half2(__float2half(e[0]), __float2half(e[1]));
    ph[2*t+1]       = __halves2half2(__float2half(e[2]), __float2half(e[3]));
    ph[512 + 2*t]   = __halves2half2(__float2half(e[4]), __float2half(e[5]));
    ph[512 + 2*t+1] = __halves2half2(__float2half(e[6]), __float2half(e[7]));
}

// ---------------- 5 weight transposes in ONE launch: W[K,N] fp32 -> WT[N,K] fp16 ----------------
__global__ void __launch_bounds__(256) wt_conv5(
    const float* __restrict__ W0, const float* __restrict__ W1,
    const float* __restrict__ W2, const float* __restrict__ W3,
    const float* __restrict__ W4, __half* __restrict__ T)
{
    const float* W;
    switch (blockIdx.z) {
        case 0: W = W0; break;
        case 1: W = W1; break;
        case 2: W = W2; break;
        case 3: W = W3; break;
        default: W = W4; break;
    }
    __half* Th = T + (size_t)blockIdx.z * WSZ;
    __shared__ float tile[64][65];
    int k0 = blockIdx.y * 64, n0 = blockIdx.x * 64;
#pragma unroll
    for (int u = threadIdx.x; u < 4096; u += 256) {
        int r = u >> 6, c = u & 63;
        tile[r][c] = W[(size_t)(k0 + r) * ND + n0 + c];
    }
    __syncthreads();
#pragma unroll
    for (int u = threadIdx.x; u < 4096; u += 256) {
        int r = u >> 6, c = u & 63;
        Th[(size_t)(n0 + r) * ND + k0 + c] = __float2half(tile[c][r]);
    }
}

// ---------------- fp16 transpose (k -> kT per batch) ----------------
__global__ void __launch_bounds__(256) kt_kernel(const __half* __restrict__ ih,
                                                 __half* __restrict__ oh)
{
    __shared__ __half th[64][65];
    int b = blockIdx.z;
    int d0 = blockIdx.x * 64, s0 = blockIdx.y * 64;
    const size_t ib = (size_t)b * NS * ND;
    const size_t ob = (size_t)b * ND * NS;
#pragma unroll
    for (int u = threadIdx.x; u < 4096; u += 256) {
        int r = u >> 6, c = u & 63;
        th[r][c] = ih[ib + (size_t)(s0 + r) * ND + d0 + c];
    }
    __syncthreads();
#pragma unroll
    for (int u = threadIdx.x; u < 4096; u += 256) {
        int r = u >> 6, c = u & 63;
        oh[ob + (size_t)(d0 + r) * NS + s0 + c] = th[c][r];
    }
}

// ---------------- driver ----------------
extern "C" void kernel_launch(void* const* d_in, const int* in_sizes, int n_in,
                              void* d_out, int out_size)
{
    const float* x    = (const float*)d_in[0];
    const int*   mask = (const int*)  d_in[1];
    const float* ln1g = (const float*)d_in[2];
    const float* ln1b = (const float*)d_in[3];
    const float* Wq   = (const float*)d_in[4];
    const float* bq   = (const float*)d_in[5];
    const float* Wk   = (const float*)d_in[6];
    const float* bk   = (const float*)d_in[7];
    const float* Wo   = (const float*)d_in[8];
    const float* bo   = (const float*)d_in[9];
    const float* ln2g = (const float*)d_in[10];
    const float* ln2b = (const float*)d_in[11];
    const float* W1   = (const float*)d_in[12];
    const float* b1   = (const float*)d_in[13];
    const float* W2   = (const float*)d_in[14];
    const float* b2   = (const float*)d_in[15];

    float* out  = (float*)d_out;
    float* wout = out + (size_t)NROWS * ND;

    __half *xn, *q, *k, *kT, *w, *at, *xn2, *h, *wt;
    float* x2;
    cudaGetSymbolAddress((void**)&xn,  g_xn);
    cudaGetSymbolAddress((void**)&q,   g_q);
    cudaGetSymbolAddress((void**)&k,   g_k);
    cudaGetSymbolAddress((void**)&kT,  g_kT);
    cudaGetSymbolAddress((void**)&w,   g_w);
    cudaGetSymbolAddress((void**)&at,  g_at);
    cudaGetSymbolAddress((void**)&xn2, g_xn2);
    cudaGetSymbolAddress((void**)&h,   g_h);
    cudaGetSymbolAddress((void**)&x2,  g_x2);
    cudaGetSymbolAddress((void**)&wt,  g_wt);

    __half *wq_t = wt + 0*WSZ;
    __half *wk_t = wt + 1*WSZ;
    __half *wo_t = wt + 2*WSZ;
    __half *w1_t = wt + 3*WSZ;
    __half *w2_t = wt + 4*WSZ;

    cudaFuncSetAttribute(gemm_tc<true,false,false,false,1>,
                         cudaFuncAttributeMaxDynamicSharedMemorySize, SMEMSZ);
    cudaFuncSetAttribute(gemm_tc<false,false,true,false,0>,
                         cudaFuncAttributeMaxDynamicSharedMemorySize, SMEMSZ);
    cudaFuncSetAttribute(gemm_tc<false,false,false,false,1>,
                         cudaFuncAttributeMaxDynamicSharedMemorySize, SMEMSZ);
    cudaFuncSetAttribute(gemm_tc<true,false,false,true,0>,
                         cudaFuncAttributeMaxDynamicSharedMemorySize, SMEMSZ);
    cudaFuncSetAttribute(gemm_tc<true,true,false,false,1>,
                         cudaFuncAttributeMaxDynamicSharedMemorySize, SMEMSZ);

    // all 5 weight transposes in one launch
    wt_conv5<<<dim3(16, 16, 5), 256>>>(Wq, Wk, Wo, W1, W2, wt);

    // 1) xn = LN1(x)
    ln_f16<<<NROWS, 256>>>(x, ln1g, ln1b, xn);

    dim3 gP(ND / 128, NROWS / 128, 1);
    // 2) q = xn@Wq+bq ; k = xn@Wk+bk  (1-pass; v == k, faithful reference bug)
    gemm_tc<true,false,false,false,1><<<gP, 256, SMEMSZ>>>(
        xn, wq_t, NROWS, ND, ND, 0, 0, 0,
        nullptr, q, bq, nullptr, nullptr, 1.f);
    gemm_tc<true,false,false,false,1><<<gP, 256, SMEMSZ>>>(
        xn, wk_t, NROWS, ND, ND, 0, 0, 0,
        nullptr, k, bk, nullptr, nullptr, 1.f);

    // 3) kT for attn@v
    kt_kernel<<<dim3(ND / 64, NS / 64, NB), 256>>>(k, kT);

    // 4) scores = (q @ k^T)/32, masked -> wout (fp32)
    dim3 gS(NS / 128, NS / 128, NB);
    gemm_tc<false,false,true,false,0><<<gS, 256, SMEMSZ>>>(
        q, k, NS, NS, ND,
        (long long)NS * ND, (long long)NS * ND, (long long)NS * NS,
        wout, nullptr, nullptr, nullptr, mask, 0.03125f);

    // 5) softmax in place + fp16 w
    softmax_f16<<<NROWS, 256>>>(wout, w);

    // 6) attn = w @ v  (v == k)
    dim3 gA(ND / 128, NS / 128, NB);
    gemm_tc<false,false,false,false,1><<<gA, 256, SMEMSZ>>>(
        w, kT, NS, ND, NS,
        (long long)NS * NS, (long long)ND * NS, (long long)NS * ND,
        nullptr, at, nullptr, nullptr, nullptr, 1.f);

    // 7) x2 = x + attn @ Wo + bo
    gemm_tc<true,false,false,true,0><<<gP, 256, SMEMSZ>>>(
        at, wo_t, NROWS, ND, ND, 0, 0, 0,
        x2, nullptr, bo, x, nullptr, 1.f);

    // 8) xn2 = LN2(x2)
    ln_f16<<<NROWS, 256>>>(x2, ln2g, ln2b, xn2);

    // 9) h = relu(xn2 @ W1 + b1)
    gemm_tc<true,true,false,false,1><<<gP, 256, SMEMSZ>>>(
        xn2, w1_t, NROWS, ND, ND, 0, 0, 0,
        nullptr, h, b1, nullptr, nullptr, 1.f);

    // 10) out = x2 + h @ W2 + b2
    gemm_tc<true,false,false,true,0><<<gP, 256, SMEMSZ>>>(
        h, w2_t, NROWS, ND, ND, 0, 0, 0,
        out, nullptr, b2, x2, nullptr, 1.f);
}